// round 2
// baseline (speedup 1.0000x reference)
#include <cuda_runtime.h>
#include <cuda_bf16.h>
#include <math.h>
#include <stdint.h>

// Problem constants (fixed shapes)
#define BATCH 2
#define SEQ   2048
#define HID   2048
#define NH    16
#define NKV   4
#define GRP   4
#define HD    128
#define MROWS (BATCH*SEQ)     // 4096

// ---------------- scratch (device globals; no allocation allowed) ----------
__device__ float g_Pl1[MROWS*HID];
__device__ float g_P  [MROWS*HID];
__device__ float g_Q  [MROWS*HID];        // [B*NH, S, HD]
__device__ float g_K  [MROWS*(NKV*HD)];   // [B*NKV, S, HD]
__device__ float g_V  [MROWS*(NKV*HD)];   // [B*NKV, S, HD]
__device__ float g_ctx[MROWS*HID];        // [B*S, H]
__device__ float g_pre[MROWS*HID];        // pre-layernorm

// =====================================================================
// Tensor-core GEMM: C = A @ B + bias, fp32 in/out, split-bf16 3-term
// A: [M,K] row-major fp32.  B: [K,N] row-major fp32.
// Block tile 128x128, K-tile 32, 256 threads (8 warps, each m64 x n32).
// Accuracy: x = hi(bf16) + lo(bf16); C = lo*hi + hi*lo + hi*hi (fp32 acc).
// modes: 0 relu, 1 +res, 2 head-scatter, 3 plain
// =====================================================================
#define AKP 40            // bf16 pitch for [m][k] / [n][k] smem planes
#define AWP 20            // 32-bit word pitch

__device__ __forceinline__ uint32_t pack_bf2(float x, float y) {
    __nv_bfloat162 h = __floats2bfloat162_rn(x, y);
    return *reinterpret_cast<uint32_t*>(&h);
}

__device__ __forceinline__ void mma_bf16(float (&d)[4],
                                         const uint32_t* a, const uint32_t* b) {
    asm volatile(
        "mma.sync.aligned.m16n8k16.row.col.f32.bf16.bf16.f32 "
        "{%0,%1,%2,%3}, {%4,%5,%6,%7}, {%8,%9}, {%0,%1,%2,%3};\n"
        : "+f"(d[0]), "+f"(d[1]), "+f"(d[2]), "+f"(d[3])
        : "r"(a[0]), "r"(a[1]), "r"(a[2]), "r"(a[3]), "r"(b[0]), "r"(b[1]));
}

__global__ __launch_bounds__(256)
void tgemm_kernel(const float* __restrict__ A, const float* __restrict__ B,
                  const float* __restrict__ bias, const float* __restrict__ res,
                  float* __restrict__ C,
                  int M, int N, int K, int mode, int heads)
{
    // smem planes: A hi/lo as [m=128][k=32] bf16 pitch 40; B hi/lo as [n=128][k=32]
    __shared__ __align__(16) uint32_t AsH[128 * AWP];
    __shared__ __align__(16) uint32_t AsL[128 * AWP];
    __shared__ __align__(16) uint32_t BsH[128 * AWP];
    __shared__ __align__(16) uint32_t BsL[128 * AWP];

    const int tid  = threadIdx.x;
    const int wid  = tid >> 5;
    const int lane = tid & 31;
    const int g    = lane >> 2;      // 0..7
    const int t    = lane & 3;       // 0..3
    const int warpM = (wid & 1) * 64;
    const int warpN = (wid >> 1) * 32;

    // global load indices
    const int aR  = tid >> 3;          // 0..31 (row within tile per pass)
    const int aC4 = (tid & 7) << 2;    // k offset 0..28
    const int bKr = tid >> 5;          // 0..7 (k row per pass)
    const int bC4 = (tid & 31) << 2;   // n offset 0..124

    const float* Ap = A + (size_t)(blockIdx.y * 128 + aR) * K + aC4;
    const float* Bp = B + (size_t)bKr * N + blockIdx.x * 128 + bC4;

    __nv_bfloat16* BsHh = reinterpret_cast<__nv_bfloat16*>(BsH);
    __nv_bfloat16* BsLh = reinterpret_cast<__nv_bfloat16*>(BsL);

    float acc[4][4][4];
    #pragma unroll
    for (int i = 0; i < 4; i++)
        #pragma unroll
        for (int j = 0; j < 4; j++)
            #pragma unroll
            for (int c = 0; c < 4; c++) acc[i][j][c] = 0.f;

    for (int kt = 0; kt < K; kt += 32) {
        // ---- load A tile 128x32, split hi/lo, store [m][k] ----
        #pragma unroll
        for (int p = 0; p < 4; p++) {
            int r = aR + p * 32;
            float4 v = *(const float4*)(Ap + (size_t)(p * 32) * K);
            float h0 = __bfloat162float(__float2bfloat16(v.x));
            float h1 = __bfloat162float(__float2bfloat16(v.y));
            float h2 = __bfloat162float(__float2bfloat16(v.z));
            float h3 = __bfloat162float(__float2bfloat16(v.w));
            int w = r * AWP + (aC4 >> 1);
            AsH[w]     = pack_bf2(h0, h1);
            AsH[w + 1] = pack_bf2(h2, h3);
            AsL[w]     = pack_bf2(v.x - h0, v.y - h1);
            AsL[w + 1] = pack_bf2(v.z - h2, v.w - h3);
        }
        // ---- load B tile 32x128, split hi/lo, store transposed [n][k] ----
        #pragma unroll
        for (int p = 0; p < 4; p++) {
            int kr = bKr + p * 8;
            float4 v = *(const float4*)(Bp + (size_t)(p * 8) * N);
            #pragma unroll
            for (int j = 0; j < 4; j++) {
                float x = (j == 0) ? v.x : (j == 1) ? v.y : (j == 2) ? v.z : v.w;
                float h = __bfloat162float(__float2bfloat16(x));
                int idx = (bC4 + j) * AKP + kr;
                BsHh[idx] = __float2bfloat16(h);
                BsLh[idx] = __float2bfloat16(x - h);
            }
        }
        __syncthreads();

        // ---- compute: 2 k16 steps ----
        #pragma unroll
        for (int ks = 0; ks < 2; ks++) {
            const int kw = ks * 8;   // word offset (16 bf16 = 8 words)
            uint32_t ah[4][4], al[4][4], bh[4][2], bl[4][2];
            #pragma unroll
            for (int mi = 0; mi < 4; mi++) {
                int r0 = (warpM + mi * 16 + g) * AWP + kw + t;
                int r1 = r0 + 8 * AWP;
                ah[mi][0] = AsH[r0];     ah[mi][1] = AsH[r1];
                ah[mi][2] = AsH[r0 + 4]; ah[mi][3] = AsH[r1 + 4];
                al[mi][0] = AsL[r0];     al[mi][1] = AsL[r1];
                al[mi][2] = AsL[r0 + 4]; al[mi][3] = AsL[r1 + 4];
            }
            #pragma unroll
            for (int ni = 0; ni < 4; ni++) {
                int c0 = (warpN + ni * 8 + g) * AWP + kw + t;
                bh[ni][0] = BsH[c0]; bh[ni][1] = BsH[c0 + 4];
                bl[ni][0] = BsL[c0]; bl[ni][1] = BsL[c0 + 4];
            }
            #pragma unroll
            for (int mi = 0; mi < 4; mi++)
                #pragma unroll
                for (int ni = 0; ni < 4; ni++) {
                    mma_bf16(acc[mi][ni], al[mi], bh[ni]);
                    mma_bf16(acc[mi][ni], ah[mi], bl[ni]);
                    mma_bf16(acc[mi][ni], ah[mi], bh[ni]);
                }
        }
        __syncthreads();
        Ap += 32;
        Bp += (size_t)32 * N;
    }

    // ---- epilogue ----
    const int rowB = blockIdx.y * 128 + warpM + g;
    const int colB = blockIdx.x * 128 + warpN + 2 * t;
    #pragma unroll
    for (int mi = 0; mi < 4; mi++) {
        #pragma unroll
        for (int ni = 0; ni < 4; ni++) {
            #pragma unroll
            for (int h = 0; h < 2; h++) {        // row pair (g, g+8)
                int r = rowB + mi * 16 + h * 8;
                #pragma unroll
                for (int q = 0; q < 2; q++) {    // col pair (2t, 2t+1)
                    int c = colB + ni * 8 + q;
                    float v = acc[mi][ni][h * 2 + q] + bias[c];
                    if (mode == 0) {
                        C[(size_t)r * N + c] = fmaxf(v, 0.f);
                    } else if (mode == 1) {
                        C[(size_t)r * N + c] = v + res[(size_t)r * N + c];
                    } else if (mode == 3) {
                        C[(size_t)r * N + c] = v;
                    } else {
                        int b = r / SEQ, s = r - b * SEQ;
                        int head = c >> 7, d = c & 127;
                        C[(((size_t)(b * heads + head)) * SEQ + s) * HD + d] = v;
                    }
                }
            }
        }
    }
}

// ---------------- Flash attention (fp32, online softmax) -------------------
#define QP 132
#define PP 68

__global__ __launch_bounds__(256, 1)
void flash_kernel(const float* __restrict__ Q, const float* __restrict__ Kt,
                  const float* __restrict__ Vt, float* __restrict__ ctx)
{
    extern __shared__ float sm[];
    float* Qs     = sm;                 // 64*132
    float* KVs    = Qs  + 64 * QP;      // 64*132 (K then V, reused)
    float* Ps     = KVs + 64 * QP;      // 64*68
    float* alphas = Ps  + 64 * PP;      // 64
    float* ls     = alphas + 64;        // 64

    const int qb = blockIdx.x;
    const int bh = blockIdx.y;
    const int b  = bh / NH;
    const int h  = bh % NH;
    const int kv = h / GRP;

    const float* Qb = Q  + ((size_t)bh * SEQ + qb * 64) * HD;
    const float* Kb = Kt + ((size_t)(b * NKV + kv) * SEQ) * HD;
    const float* Vb = Vt + ((size_t)(b * NKV + kv) * SEQ) * HD;

    const int tid = threadIdx.x;
    const int tx  = tid & 15;
    const int ty  = tid >> 4;

    #pragma unroll
    for (int t = 0; t < 8; t++) {
        int idx4 = tid + t * 256;
        int r  = idx4 >> 5;
        int c4 = (idx4 & 31) << 2;
        *(float4*)&Qs[r * QP + c4] = *(const float4*)(Qb + (size_t)r * HD + c4);
    }

    float m_row = -INFINITY, l_row = 0.f;
    float o[4][8];
    #pragma unroll
    for (int i = 0; i < 4; i++)
        #pragma unroll
        for (int c = 0; c < 8; c++) o[i][c] = 0.f;

    const float scale = 0.08838834764831845f;

    for (int kc = 0; kc < SEQ; kc += 64) {
        __syncthreads();
        #pragma unroll
        for (int t = 0; t < 8; t++) {
            int idx4 = tid + t * 256;
            int r  = idx4 >> 5;
            int c4 = (idx4 & 31) << 2;
            *(float4*)&KVs[r * QP + c4] =
                *(const float4*)(Kb + (size_t)(kc + r) * HD + c4);
        }
        __syncthreads();

        float sacc[4][4];
        #pragma unroll
        for (int i = 0; i < 4; i++)
            #pragma unroll
            for (int j = 0; j < 4; j++) sacc[i][j] = 0.f;
        for (int d = 0; d < HD; d += 4) {
            float4 qv[4], kv4[4];
            #pragma unroll
            for (int i = 0; i < 4; i++)
                qv[i] = *(const float4*)&Qs[(ty * 4 + i) * QP + d];
            #pragma unroll
            for (int j = 0; j < 4; j++)
                kv4[j] = *(const float4*)&KVs[(tx * 4 + j) * QP + d];
            #pragma unroll
            for (int i = 0; i < 4; i++)
                #pragma unroll
                for (int j = 0; j < 4; j++) {
                    sacc[i][j] = fmaf(qv[i].x, kv4[j].x, sacc[i][j]);
                    sacc[i][j] = fmaf(qv[i].y, kv4[j].y, sacc[i][j]);
                    sacc[i][j] = fmaf(qv[i].z, kv4[j].z, sacc[i][j]);
                    sacc[i][j] = fmaf(qv[i].w, kv4[j].w, sacc[i][j]);
                }
        }
        #pragma unroll
        for (int i = 0; i < 4; i++)
            #pragma unroll
            for (int j = 0; j < 4; j++)
                Ps[(ty * 4 + i) * PP + tx * 4 + j] = sacc[i][j] * scale;
        __syncthreads();

        if (tid < 64) {
            float rmax = -INFINITY;
            #pragma unroll 8
            for (int j = 0; j < 64; j++) rmax = fmaxf(rmax, Ps[tid * PP + j]);
            float mnew  = fmaxf(m_row, rmax);
            float alpha = expf(m_row - mnew);
            float sum = 0.f;
            #pragma unroll 8
            for (int j = 0; j < 64; j++) {
                float p = expf(Ps[tid * PP + j] - mnew);
                Ps[tid * PP + j] = p;
                sum += p;
            }
            l_row = l_row * alpha + sum;
            m_row = mnew;
            alphas[tid] = alpha;
        }
        __syncthreads();

        #pragma unroll
        for (int i = 0; i < 4; i++) {
            float a = alphas[ty * 4 + i];
            #pragma unroll
            for (int c = 0; c < 8; c++) o[i][c] *= a;
        }

        #pragma unroll
        for (int t = 0; t < 8; t++) {
            int idx4 = tid + t * 256;
            int r  = idx4 >> 5;
            int c4 = (idx4 & 31) << 2;
            *(float4*)&KVs[r * QP + c4] =
                *(const float4*)(Vb + (size_t)(kc + r) * HD + c4);
        }
        __syncthreads();

        for (int j = 0; j < 64; j++) {
            float p[4];
            #pragma unroll
            for (int i = 0; i < 4; i++) p[i] = Ps[(ty * 4 + i) * PP + j];
            float4 v0 = *(const float4*)&KVs[j * QP + tx * 8];
            float4 v1 = *(const float4*)&KVs[j * QP + tx * 8 + 4];
            #pragma unroll
            for (int i = 0; i < 4; i++) {
                o[i][0] = fmaf(p[i], v0.x, o[i][0]);
                o[i][1] = fmaf(p[i], v0.y, o[i][1]);
                o[i][2] = fmaf(p[i], v0.z, o[i][2]);
                o[i][3] = fmaf(p[i], v0.w, o[i][3]);
                o[i][4] = fmaf(p[i], v1.x, o[i][4]);
                o[i][5] = fmaf(p[i], v1.y, o[i][5]);
                o[i][6] = fmaf(p[i], v1.z, o[i][6]);
                o[i][7] = fmaf(p[i], v1.w, o[i][7]);
            }
        }
    }

    __syncthreads();
    if (tid < 64) ls[tid] = l_row;
    __syncthreads();

    #pragma unroll
    for (int i = 0; i < 4; i++) {
        float inv = 1.f / ls[ty * 4 + i];
        int q = qb * 64 + ty * 4 + i;
        float* dst = ctx + ((size_t)(b * SEQ + q)) * HID + h * HD + tx * 8;
        float4 w0 = make_float4(o[i][0]*inv, o[i][1]*inv, o[i][2]*inv, o[i][3]*inv);
        float4 w1 = make_float4(o[i][4]*inv, o[i][5]*inv, o[i][6]*inv, o[i][7]*inv);
        *(float4*)(dst)     = w0;
        *(float4*)(dst + 4) = w1;
    }
}

// ---------------- residual + layernorm -------------------------------------
__device__ __forceinline__ float block_sum256(float v, float* sred)
{
    #pragma unroll
    for (int off = 16; off; off >>= 1) v += __shfl_xor_sync(0xffffffffu, v, off);
    int warp = threadIdx.x >> 5;
    if ((threadIdx.x & 31) == 0) sred[warp] = v;
    __syncthreads();
    if (threadIdx.x < 32) {
        float x = (threadIdx.x < 8) ? sred[threadIdx.x] : 0.f;
        #pragma unroll
        for (int off = 4; off; off >>= 1) x += __shfl_xor_sync(0xffffffffu, x, off);
        if (threadIdx.x == 0) sred[0] = x;
    }
    __syncthreads();
    float r = sred[0];
    __syncthreads();
    return r;
}

__global__ __launch_bounds__(256)
void ln_kernel(const float* __restrict__ x, const float* __restrict__ resid,
               const float* __restrict__ gamma, const float* __restrict__ beta,
               float* __restrict__ out)
{
    __shared__ float sred[32];
    const size_t row = blockIdx.x;
    const int tid = threadIdx.x;
    const float* xr = x     + row * HID;
    const float* rr = resid + row * HID;

    float v[8];
    float s = 0.f;
    #pragma unroll
    for (int t = 0; t < 8; t++) {
        int c = tid + t * 256;
        v[t] = xr[c] + rr[c];
        s += v[t];
    }
    float mean = block_sum256(s, sred) * (1.f / HID);

    float s2 = 0.f;
    #pragma unroll
    for (int t = 0; t < 8; t++) { float d = v[t] - mean; s2 += d * d; }
    float var = block_sum256(s2, sred) * (1.f / HID);
    float rstd = rsqrtf(var + 1e-12f);

    float* orow = out + row * HID;
    #pragma unroll
    for (int t = 0; t < 8; t++) {
        int c = tid + t * 256;
        orow[c] = (v[t] - mean) * rstd * gamma[c] + beta[c];
    }
}

// ---------------- launch ----------------------------------------------------
extern "C" void kernel_launch(void* const* d_in, const int* in_sizes, int n_in,
                              void* d_out, int out_size)
{
    const float* hidden = (const float*)d_in[0];
    const float* src    = (const float*)d_in[1];
    const float* Wq = (const float*)d_in[2];
    const float* bq = (const float*)d_in[3];
    const float* Wk = (const float*)d_in[4];
    const float* bk = (const float*)d_in[5];
    const float* Wv = (const float*)d_in[6];
    const float* bv = (const float*)d_in[7];
    const float* Wd = (const float*)d_in[8];
    const float* bd = (const float*)d_in[9];
    const float* W1 = (const float*)d_in[10];
    const float* b1 = (const float*)d_in[11];
    const float* W2 = (const float*)d_in[12];
    const float* b2 = (const float*)d_in[13];
    const float* gamma = (const float*)d_in[14];
    const float* beta  = (const float*)d_in[15];
    float* out = (float*)d_out;

    float *pPl1, *pP, *pQ, *pK, *pV, *pCtx, *pPre;
    cudaGetSymbolAddress((void**)&pPl1, g_Pl1);
    cudaGetSymbolAddress((void**)&pP,   g_P);
    cudaGetSymbolAddress((void**)&pQ,   g_Q);
    cudaGetSymbolAddress((void**)&pK,   g_K);
    cudaGetSymbolAddress((void**)&pV,   g_V);
    cudaGetSymbolAddress((void**)&pCtx, g_ctx);
    cudaGetSymbolAddress((void**)&pPre, g_pre);

    dim3 blk(256);
    // 1. Pl1 = relu(src @ W1 + b1)
    tgemm_kernel<<<dim3(HID/128, MROWS/128), blk>>>(src, W1, b1, nullptr, pPl1,
                                                    MROWS, HID, HID, 0, 0);
    // 2. P = (Pl1 @ W2 + b2) + Pl1
    tgemm_kernel<<<dim3(HID/128, MROWS/128), blk>>>(pPl1, W2, b2, pPl1, pP,
                                                    MROWS, HID, HID, 1, 0);
    // 3. K = P @ Wk + bk  -> [B*NKV, S, HD]
    tgemm_kernel<<<dim3((NKV*HD)/128, MROWS/128), blk>>>(pP, Wk, bk, nullptr, pK,
                                                    MROWS, NKV*HD, HID, 2, NKV);
    // 4. V = P @ Wv + bv  -> [B*NKV, S, HD]
    tgemm_kernel<<<dim3((NKV*HD)/128, MROWS/128), blk>>>(pP, Wv, bv, nullptr, pV,
                                                    MROWS, NKV*HD, HID, 2, NKV);
    // 5. Q = hidden @ Wq + bq  -> [B*NH, S, HD]
    tgemm_kernel<<<dim3(HID/128, MROWS/128), blk>>>(hidden, Wq, bq, nullptr, pQ,
                                                    MROWS, HID, HID, 2, NH);
    // 6. flash attention -> ctx [B*S, H]
    size_t shmem = (size_t)(64*QP*2 + 64*PP + 128) * sizeof(float);
    cudaFuncSetAttribute(flash_kernel, cudaFuncAttributeMaxDynamicSharedMemorySize,
                         (int)shmem);
    flash_kernel<<<dim3(SEQ/64, BATCH*NH), blk, shmem>>>(pQ, pK, pV, pCtx);
    // 7. pre = ctx @ Wd + bd
    tgemm_kernel<<<dim3(HID/128, MROWS/128), blk>>>(pCtx, Wd, bd, nullptr, pPre,
                                                    MROWS, HID, HID, 3, 0);
    // 8. out = layernorm(pre + hidden)
    ln_kernel<<<MROWS, 256>>>(pPre, hidden, gamma, beta, out);
}

// round 4
// speedup vs baseline: 1.4874x; 1.4874x over previous
#include <cuda_runtime.h>
#include <cuda_bf16.h>
#include <math.h>
#include <stdint.h>

// Problem constants (fixed shapes)
#define BATCH 2
#define SEQ   2048
#define HID   2048
#define NH    16
#define NKV   4
#define GRP   4
#define HD    128
#define MROWS (BATCH*SEQ)     // 4096
#define KDIM  2048            // all GEMMs have K = 2048

typedef __nv_bfloat16 bf16;

// ---------------- scratch (device globals; no allocation allowed) ----------
__device__ float g_Pl1[MROWS*HID];             // fp32 (residual input of gemm2)
__device__ float g_Q  [MROWS*HID];             // [B*NH, S, HD]
__device__ float g_K  [MROWS*(NKV*HD)];        // [B*NKV, S, HD]
__device__ float g_V  [MROWS*(NKV*HD)];        // [B*NKV, S, HD]
__device__ float g_pre[MROWS*HID];             // pre-layernorm

// split activations (row-major [M][K])
__device__ __align__(16) bf16 g_srcH[MROWS*HID], g_srcL[MROWS*HID];
__device__ __align__(16) bf16 g_hidH[MROWS*HID], g_hidL[MROWS*HID];
__device__ __align__(16) bf16 g_Pl1H[MROWS*HID], g_Pl1L[MROWS*HID];
__device__ __align__(16) bf16 g_PH  [MROWS*HID], g_PL  [MROWS*HID];
__device__ __align__(16) bf16 g_ctxH[MROWS*HID], g_ctxL[MROWS*HID];

// transposed split weights ([N][K])
__device__ __align__(16) bf16 g_WqtH[HID*HID],        g_WqtL[HID*HID];
__device__ __align__(16) bf16 g_WktH[(NKV*HD)*HID],   g_WktL[(NKV*HD)*HID];
__device__ __align__(16) bf16 g_WvtH[(NKV*HD)*HID],   g_WvtL[(NKV*HD)*HID];
__device__ __align__(16) bf16 g_WdtH[HID*HID],        g_WdtL[HID*HID];
__device__ __align__(16) bf16 g_W1tH[HID*HID],        g_W1tL[HID*HID];
__device__ __align__(16) bf16 g_W2tH[HID*HID],        g_W2tL[HID*HID];

// ================= helpers ==================================================
__device__ __forceinline__ void mma_bf16(float (&d)[4],
                                         const uint32_t* a, const uint32_t* b) {
    asm volatile(
        "mma.sync.aligned.m16n8k16.row.col.f32.bf16.bf16.f32 "
        "{%0,%1,%2,%3}, {%4,%5,%6,%7}, {%8,%9}, {%0,%1,%2,%3};\n"
        : "+f"(d[0]), "+f"(d[1]), "+f"(d[2]), "+f"(d[3])
        : "r"(a[0]), "r"(a[1]), "r"(a[2]), "r"(a[3]), "r"(b[0]), "r"(b[1]));
}

__device__ __forceinline__ void ldsm4(uint32_t* r, uint32_t addr) {
    asm volatile("ldmatrix.sync.aligned.m8n8.x4.shared.b16 {%0,%1,%2,%3}, [%4];"
        : "=r"(r[0]), "=r"(r[1]), "=r"(r[2]), "=r"(r[3]) : "r"(addr));
}

__device__ __forceinline__ void cp16(uint32_t dst, const void* src) {
    asm volatile("cp.async.cg.shared.global [%0], [%1], 16;" :: "r"(dst), "l"(src));
}

// ================= split kernels ============================================
__global__ __launch_bounds__(256)
void split_kernel(const float* __restrict__ x, bf16* __restrict__ hi,
                  bf16* __restrict__ lo, int n4)
{
    int i = blockIdx.x * blockDim.x + threadIdx.x;
    if (i >= n4) return;
    float4 v = ((const float4*)x)[i];
    bf16 h0 = __float2bfloat16(v.x), h1 = __float2bfloat16(v.y);
    bf16 h2 = __float2bfloat16(v.z), h3 = __float2bfloat16(v.w);
    __nv_bfloat162 a, b;
    a.x = h0; a.y = h1; b.x = h2; b.y = h3;
    ((__nv_bfloat162*)hi)[2*i]   = a;
    ((__nv_bfloat162*)hi)[2*i+1] = b;
    a.x = __float2bfloat16(v.x - __bfloat162float(h0));
    a.y = __float2bfloat16(v.y - __bfloat162float(h1));
    b.x = __float2bfloat16(v.z - __bfloat162float(h2));
    b.y = __float2bfloat16(v.w - __bfloat162float(h3));
    ((__nv_bfloat162*)lo)[2*i]   = a;
    ((__nv_bfloat162*)lo)[2*i+1] = b;
}

// W [K][N] fp32 -> WtH/WtL [N][K] bf16 (transpose + split)
__global__ __launch_bounds__(256)
void tsplit_kernel(const float* __restrict__ W, bf16* __restrict__ TH,
                   bf16* __restrict__ TL, int Kd, int Nd)
{
    __shared__ float tl[32][33];
    int n0 = blockIdx.x * 32, k0 = blockIdx.y * 32;
    int tx = threadIdx.x & 31;
    int ty = threadIdx.x >> 5;      // 0..7
    #pragma unroll
    for (int i = 0; i < 4; i++)
        tl[ty + 8*i][tx] = W[(size_t)(k0 + ty + 8*i) * Nd + n0 + tx];
    __syncthreads();
    #pragma unroll
    for (int i = 0; i < 4; i++) {
        float v = tl[tx][ty + 8*i];
        bf16 h = __float2bfloat16(v);
        size_t o = (size_t)(n0 + ty + 8*i) * Kd + k0 + tx;
        TH[o] = h;
        TL[o] = __float2bfloat16(v - __bfloat162float(h));
    }
}

// ================= split-bf16 tensor GEMM ===================================
// A (hi/lo): [M][K] bf16. Bt (hi/lo): [N][K] bf16. C = A@B + bias.
// Block tile 128x128, ktile 32, 8 warps (64x32 each), 2-stage cp.async.
#define PITCHB 80        // smem row pitch (bytes) for 32 bf16 + pad
#define PLANE  10240     // 128 * 80
#define STAGEB 40960     // 4 planes
#define SM_TOT (2*STAGEB)

#define M_RELU    1
#define M_RES     2
#define M_SCATTER 4
#define M_WRITEC  8
#define M_SPLIT   16

__global__ __launch_bounds__(256)
void bgemm_kernel(const bf16* __restrict__ AH, const bf16* __restrict__ AL,
                  const bf16* __restrict__ BtH, const bf16* __restrict__ BtL,
                  const float* __restrict__ bias, const float* __restrict__ res,
                  float* __restrict__ C, bf16* __restrict__ CH, bf16* __restrict__ CL,
                  int N, int mode, int heads)
{
    extern __shared__ char smraw[];
    const uint32_t sbase = (uint32_t)__cvta_generic_to_shared(smraw);

    const int tid  = threadIdx.x;
    const int wid  = tid >> 5;
    const int lane = tid & 31;
    const int warpM = (wid & 1) * 64;
    const int warpN = (wid >> 1) * 32;
    const int mBase = blockIdx.y * 128;
    const int nBase = blockIdx.x * 128;

    // global->smem load mapping: thread covers 32B (2 x 16B) of one row per plane
    const int lrow = tid >> 1;
    const int lcb  = (tid & 1) * 32;
    const size_t aOffG = (size_t)(mBase + lrow) * KDIM;
    const size_t bOffG = (size_t)(nBase + lrow) * KDIM;
    const uint32_t sRow = (uint32_t)(lrow * PITCHB + lcb);

    // ldmatrix fragment smem offsets
    const int l15 = lane & 15;
    const int l16 = (lane >> 4) * 16;
    uint32_t aoff[4], boff[2];
    #pragma unroll
    for (int mi = 0; mi < 4; mi++)
        aoff[mi] = (uint32_t)((warpM + mi*16 + l15) * PITCHB + l16);
    #pragma unroll
    for (int n2 = 0; n2 < 2; n2++)
        boff[n2] = (uint32_t)((warpN + n2*16 + l15) * PITCHB + l16);

    float acc[4][4][4];
    #pragma unroll
    for (int i = 0; i < 4; i++)
        #pragma unroll
        for (int j = 0; j < 4; j++)
            #pragma unroll
            for (int c = 0; c < 4; c++) acc[i][j][c] = 0.f;

#define LOADSTAGE(kt, buf) do {                                                \
        uint32_t sb_ = sbase + (buf)*STAGEB + sRow;                            \
        const char* ga  = (const char*)(AH  + aOffG + (kt)*32) + lcb;          \
        const char* gal = (const char*)(AL  + aOffG + (kt)*32) + lcb;          \
        const char* gb  = (const char*)(BtH + bOffG + (kt)*32) + lcb;          \
        const char* gbl = (const char*)(BtL + bOffG + (kt)*32) + lcb;          \
        cp16(sb_,              ga);  cp16(sb_ + 16,            ga  + 16);      \
        cp16(sb_ +   PLANE,    gal); cp16(sb_ +   PLANE + 16,  gal + 16);      \
        cp16(sb_ + 2*PLANE,    gb);  cp16(sb_ + 2*PLANE + 16,  gb  + 16);      \
        cp16(sb_ + 3*PLANE,    gbl); cp16(sb_ + 3*PLANE + 16,  gbl + 16);      \
    } while (0)

    const int nk = KDIM / 32;
    LOADSTAGE(0, 0);
    asm volatile("cp.async.commit_group;" ::: "memory");

    for (int kt = 0; kt < nk; kt++) {
        const int buf = kt & 1;
        asm volatile("cp.async.wait_group 0;" ::: "memory");
        __syncthreads();
        if (kt + 1 < nk) {
            LOADSTAGE(kt + 1, buf ^ 1);
            asm volatile("cp.async.commit_group;" ::: "memory");
        }
        const uint32_t sb = sbase + buf * STAGEB;

        #pragma unroll
        for (int ks = 0; ks < 2; ks++) {
            const int kb = ks * 32;
            uint32_t ah[4][4], al[4][4], bh[4][2], bl[4][2];
            #pragma unroll
            for (int mi = 0; mi < 4; mi++) {
                ldsm4(ah[mi], sb + aoff[mi] + kb);
                ldsm4(al[mi], sb + PLANE + aoff[mi] + kb);
            }
            #pragma unroll
            for (int n2 = 0; n2 < 2; n2++) {
                uint32_t r[4];
                ldsm4(r, sb + 2*PLANE + boff[n2] + kb);
                bh[2*n2][0]   = r[0]; bh[2*n2][1]   = r[2];
                bh[2*n2+1][0] = r[1]; bh[2*n2+1][1] = r[3];
                ldsm4(r, sb + 3*PLANE + boff[n2] + kb);
                bl[2*n2][0]   = r[0]; bl[2*n2][1]   = r[2];
                bl[2*n2+1][0] = r[1]; bl[2*n2+1][1] = r[3];
            }
            #pragma unroll
            for (int mi = 0; mi < 4; mi++)
                #pragma unroll
                for (int ni = 0; ni < 4; ni++) {
                    mma_bf16(acc[mi][ni], al[mi], bh[ni]);
                    mma_bf16(acc[mi][ni], ah[mi], bl[ni]);
                    mma_bf16(acc[mi][ni], ah[mi], bh[ni]);
                }
        }
    }
#undef LOADSTAGE

    // -------- epilogue --------
    const int g  = lane >> 2;
    const int t4 = lane & 3;
    const int rw = mBase + warpM + g;
    const int cw = nBase + warpN + 2 * t4;
    #pragma unroll
    for (int mi = 0; mi < 4; mi++) {
        #pragma unroll
        for (int h = 0; h < 2; h++) {
            const int r = rw + mi * 16 + h * 8;
            #pragma unroll
            for (int ni = 0; ni < 4; ni++) {
                const int c0 = cw + ni * 8;
                float v0 = acc[mi][ni][h*2 + 0] + bias[c0];
                float v1 = acc[mi][ni][h*2 + 1] + bias[c0 + 1];
                if (mode & M_RELU) { v0 = fmaxf(v0, 0.f); v1 = fmaxf(v1, 0.f); }
                if (mode & M_RES) {
                    v0 += res[(size_t)r * N + c0];
                    v1 += res[(size_t)r * N + c0 + 1];
                }
                if (mode & M_SCATTER) {
                    int b = r / SEQ, s = r - b * SEQ;
                    int head = c0 >> 7, d = c0 & 127;
                    size_t o = (((size_t)(b * heads + head)) * SEQ + s) * HD + d;
                    C[o] = v0; C[o + 1] = v1;
                } else if (mode & M_WRITEC) {
                    C[(size_t)r * N + c0]     = v0;
                    C[(size_t)r * N + c0 + 1] = v1;
                }
                if (mode & M_SPLIT) {
                    bf16 b0 = __float2bfloat16(v0), b1 = __float2bfloat16(v1);
                    __nv_bfloat162 ph; ph.x = b0; ph.y = b1;
                    __nv_bfloat162 pl;
                    pl.x = __float2bfloat16(v0 - __bfloat162float(b0));
                    pl.y = __float2bfloat16(v1 - __bfloat162float(b1));
                    *(__nv_bfloat162*)(CH + (size_t)r * N + c0) = ph;
                    *(__nv_bfloat162*)(CL + (size_t)r * N + c0) = pl;
                }
            }
        }
    }
}

// ---------------- Flash attention (fp32, online softmax) -------------------
#define QP 132
#define PP 68

__global__ __launch_bounds__(256, 1)
void flash_kernel(const float* __restrict__ Q, const float* __restrict__ Kt,
                  const float* __restrict__ Vt,
                  bf16* __restrict__ ctxH, bf16* __restrict__ ctxL)
{
    extern __shared__ float sm[];
    float* Qs     = sm;                 // 64*132
    float* KVs    = Qs  + 64 * QP;      // 64*132
    float* Ps     = KVs + 64 * QP;      // 64*68
    float* alphas = Ps  + 64 * PP;      // 64
    float* ls     = alphas + 64;        // 64

    const int qb = blockIdx.x;
    const int bh = blockIdx.y;
    const int b  = bh / NH;
    const int h  = bh % NH;
    const int kvh = h / GRP;

    const float* Qb = Q  + ((size_t)bh * SEQ + qb * 64) * HD;
    const float* Kb = Kt + ((size_t)(b * NKV + kvh) * SEQ) * HD;
    const float* Vb = Vt + ((size_t)(b * NKV + kvh) * SEQ) * HD;

    const int tid = threadIdx.x;
    const int tx  = tid & 15;
    const int ty  = tid >> 4;

    #pragma unroll
    for (int t = 0; t < 8; t++) {
        int idx4 = tid + t * 256;
        int r  = idx4 >> 5;
        int c4 = (idx4 & 31) << 2;
        *(float4*)&Qs[r * QP + c4] = *(const float4*)(Qb + (size_t)r * HD + c4);
    }

    float m_row = -INFINITY, l_row = 0.f;
    float o[4][8];
    #pragma unroll
    for (int i = 0; i < 4; i++)
        #pragma unroll
        for (int c = 0; c < 8; c++) o[i][c] = 0.f;

    const float scale = 0.08838834764831845f;

    for (int kc = 0; kc < SEQ; kc += 64) {
        __syncthreads();
        #pragma unroll
        for (int t = 0; t < 8; t++) {
            int idx4 = tid + t * 256;
            int r  = idx4 >> 5;
            int c4 = (idx4 & 31) << 2;
            *(float4*)&KVs[r * QP + c4] =
                *(const float4*)(Kb + (size_t)(kc + r) * HD + c4);
        }
        __syncthreads();

        float sacc[4][4];
        #pragma unroll
        for (int i = 0; i < 4; i++)
            #pragma unroll
            for (int j = 0; j < 4; j++) sacc[i][j] = 0.f;
        for (int d = 0; d < HD; d += 4) {
            float4 qv[4], kv4[4];
            #pragma unroll
            for (int i = 0; i < 4; i++)
                qv[i] = *(const float4*)&Qs[(ty * 4 + i) * QP + d];
            #pragma unroll
            for (int j = 0; j < 4; j++)
                kv4[j] = *(const float4*)&KVs[(tx * 4 + j) * QP + d];
            #pragma unroll
            for (int i = 0; i < 4; i++)
                #pragma unroll
                for (int j = 0; j < 4; j++) {
                    sacc[i][j] = fmaf(qv[i].x, kv4[j].x, sacc[i][j]);
                    sacc[i][j] = fmaf(qv[i].y, kv4[j].y, sacc[i][j]);
                    sacc[i][j] = fmaf(qv[i].z, kv4[j].z, sacc[i][j]);
                    sacc[i][j] = fmaf(qv[i].w, kv4[j].w, sacc[i][j]);
                }
        }
        #pragma unroll
        for (int i = 0; i < 4; i++)
            #pragma unroll
            for (int j = 0; j < 4; j++)
                Ps[(ty * 4 + i) * PP + tx * 4 + j] = sacc[i][j] * scale;
        __syncthreads();

        if (tid < 64) {
            float rmax = -INFINITY;
            #pragma unroll 8
            for (int j = 0; j < 64; j++) rmax = fmaxf(rmax, Ps[tid * PP + j]);
            float mnew  = fmaxf(m_row, rmax);
            float alpha = expf(m_row - mnew);
            float sum = 0.f;
            #pragma unroll 8
            for (int j = 0; j < 64; j++) {
                float p = expf(Ps[tid * PP + j] - mnew);
                Ps[tid * PP + j] = p;
                sum += p;
            }
            l_row = l_row * alpha + sum;
            m_row = mnew;
            alphas[tid] = alpha;
        }
        __syncthreads();

        #pragma unroll
        for (int i = 0; i < 4; i++) {
            float a = alphas[ty * 4 + i];
            #pragma unroll
            for (int c = 0; c < 8; c++) o[i][c] *= a;
        }

        #pragma unroll
        for (int t = 0; t < 8; t++) {
            int idx4 = tid + t * 256;
            int r  = idx4 >> 5;
            int c4 = (idx4 & 31) << 2;
            *(float4*)&KVs[r * QP + c4] =
                *(const float4*)(Vb + (size_t)(kc + r) * HD + c4);
        }
        __syncthreads();

        for (int j = 0; j < 64; j++) {
            float p[4];
            #pragma unroll
            for (int i = 0; i < 4; i++) p[i] = Ps[(ty * 4 + i) * PP + j];
            float4 v0 = *(const float4*)&KVs[j * QP + tx * 8];
            float4 v1 = *(const float4*)&KVs[j * QP + tx * 8 + 4];
            #pragma unroll
            for (int i = 0; i < 4; i++) {
                o[i][0] = fmaf(p[i], v0.x, o[i][0]);
                o[i][1] = fmaf(p[i], v0.y, o[i][1]);
                o[i][2] = fmaf(p[i], v0.z, o[i][2]);
                o[i][3] = fmaf(p[i], v0.w, o[i][3]);
                o[i][4] = fmaf(p[i], v1.x, o[i][4]);
                o[i][5] = fmaf(p[i], v1.y, o[i][5]);
                o[i][6] = fmaf(p[i], v1.z, o[i][6]);
                o[i][7] = fmaf(p[i], v1.w, o[i][7]);
            }
        }
    }

    __syncthreads();
    if (tid < 64) ls[tid] = l_row;
    __syncthreads();

    #pragma unroll
    for (int i = 0; i < 4; i++) {
        float inv = 1.f / ls[ty * 4 + i];
        int q = qb * 64 + ty * 4 + i;
        size_t off = ((size_t)(b * SEQ + q)) * HID + h * HD + tx * 8;
        #pragma unroll
        for (int p = 0; p < 4; p++) {
            float v0 = o[i][2*p] * inv, v1 = o[i][2*p + 1] * inv;
            bf16 b0 = __float2bfloat16(v0), b1 = __float2bfloat16(v1);
            __nv_bfloat162 ph; ph.x = b0; ph.y = b1;
            __nv_bfloat162 pl;
            pl.x = __float2bfloat16(v0 - __bfloat162float(b0));
            pl.y = __float2bfloat16(v1 - __bfloat162float(b1));
            *(__nv_bfloat162*)(ctxH + off + 2*p) = ph;
            *(__nv_bfloat162*)(ctxL + off + 2*p) = pl;
        }
    }
}

// ---------------- residual + layernorm -------------------------------------
__device__ __forceinline__ float block_sum256(float v, float* sred)
{
    #pragma unroll
    for (int off = 16; off; off >>= 1) v += __shfl_xor_sync(0xffffffffu, v, off);
    int warp = threadIdx.x >> 5;
    if ((threadIdx.x & 31) == 0) sred[warp] = v;
    __syncthreads();
    if (threadIdx.x < 32) {
        float x = (threadIdx.x < 8) ? sred[threadIdx.x] : 0.f;
        #pragma unroll
        for (int off = 4; off; off >>= 1) x += __shfl_xor_sync(0xffffffffu, x, off);
        if (threadIdx.x == 0) sred[0] = x;
    }
    __syncthreads();
    float r = sred[0];
    __syncthreads();
    return r;
}

__global__ __launch_bounds__(256)
void ln_kernel(const float* __restrict__ x, const float* __restrict__ resid,
               const float* __restrict__ gamma, const float* __restrict__ beta,
               float* __restrict__ out)
{
    __shared__ float sred[32];
    const size_t row = blockIdx.x;
    const int tid = threadIdx.x;
    const float* xr = x     + row * HID;
    const float* rr = resid + row * HID;

    float v[8];
    float s = 0.f;
    #pragma unroll
    for (int t = 0; t < 8; t++) {
        int c = tid + t * 256;
        v[t] = xr[c] + rr[c];
        s += v[t];
    }
    float mean = block_sum256(s, sred) * (1.f / HID);

    float s2 = 0.f;
    #pragma unroll
    for (int t = 0; t < 8; t++) { float d = v[t] - mean; s2 += d * d; }
    float var = block_sum256(s2, sred) * (1.f / HID);
    float rstd = rsqrtf(var + 1e-12f);

    float* orow = out + row * HID;
    #pragma unroll
    for (int t = 0; t < 8; t++) {
        int c = tid + t * 256;
        orow[c] = (v[t] - mean) * rstd * gamma[c] + beta[c];
    }
}

// ---------------- launch ----------------------------------------------------
extern "C" void kernel_launch(void* const* d_in, const int* in_sizes, int n_in,
                              void* d_out, int out_size)
{
    const float* hidden = (const float*)d_in[0];
    const float* src    = (const float*)d_in[1];
    const float* Wq = (const float*)d_in[2];
    const float* bq = (const float*)d_in[3];
    const float* Wk = (const float*)d_in[4];
    const float* bk = (const float*)d_in[5];
    const float* Wv = (const float*)d_in[6];
    const float* bv = (const float*)d_in[7];
    const float* Wd = (const float*)d_in[8];
    const float* bd = (const float*)d_in[9];
    const float* W1 = (const float*)d_in[10];
    const float* b1 = (const float*)d_in[11];
    const float* W2 = (const float*)d_in[12];
    const float* b2 = (const float*)d_in[13];
    const float* gamma = (const float*)d_in[14];
    const float* beta  = (const float*)d_in[15];
    float* out = (float*)d_out;

    float *pPl1, *pQ, *pK, *pV, *pPre;
    cudaGetSymbolAddress((void**)&pPl1, g_Pl1);
    cudaGetSymbolAddress((void**)&pQ,   g_Q);
    cudaGetSymbolAddress((void**)&pK,   g_K);
    cudaGetSymbolAddress((void**)&pV,   g_V);
    cudaGetSymbolAddress((void**)&pPre, g_pre);

    bf16 *srcH, *srcL, *hidH, *hidL, *Pl1H, *Pl1L, *PH, *PL, *ctxH, *ctxL;
    cudaGetSymbolAddress((void**)&srcH, g_srcH); cudaGetSymbolAddress((void**)&srcL, g_srcL);
    cudaGetSymbolAddress((void**)&hidH, g_hidH); cudaGetSymbolAddress((void**)&hidL, g_hidL);
    cudaGetSymbolAddress((void**)&Pl1H, g_Pl1H); cudaGetSymbolAddress((void**)&Pl1L, g_Pl1L);
    cudaGetSymbolAddress((void**)&PH,   g_PH);   cudaGetSymbolAddress((void**)&PL,   g_PL);
    cudaGetSymbolAddress((void**)&ctxH, g_ctxH); cudaGetSymbolAddress((void**)&ctxL, g_ctxL);

    bf16 *WqtH,*WqtL,*WktH,*WktL,*WvtH,*WvtL,*WdtH,*WdtL,*W1tH,*W1tL,*W2tH,*W2tL;
    cudaGetSymbolAddress((void**)&WqtH, g_WqtH); cudaGetSymbolAddress((void**)&WqtL, g_WqtL);
    cudaGetSymbolAddress((void**)&WktH, g_WktH); cudaGetSymbolAddress((void**)&WktL, g_WktL);
    cudaGetSymbolAddress((void**)&WvtH, g_WvtH); cudaGetSymbolAddress((void**)&WvtL, g_WvtL);
    cudaGetSymbolAddress((void**)&WdtH, g_WdtH); cudaGetSymbolAddress((void**)&WdtL, g_WdtL);
    cudaGetSymbolAddress((void**)&W1tH, g_W1tH); cudaGetSymbolAddress((void**)&W1tL, g_W1tL);
    cudaGetSymbolAddress((void**)&W2tH, g_W2tH); cudaGetSymbolAddress((void**)&W2tL, g_W2tL);

    cudaFuncSetAttribute(bgemm_kernel, cudaFuncAttributeMaxDynamicSharedMemorySize, SM_TOT);
    size_t fshmem = (size_t)(64*QP*2 + 64*PP + 128) * sizeof(float);
    cudaFuncSetAttribute(flash_kernel, cudaFuncAttributeMaxDynamicSharedMemorySize, (int)fshmem);

    dim3 blk(256);
    const int n4 = MROWS * HID / 4;

    // input splits
    split_kernel<<<n4/256, blk>>>(src,    srcH, srcL, n4);
    split_kernel<<<n4/256, blk>>>(hidden, hidH, hidL, n4);
    // weight transpose-splits
    tsplit_kernel<<<dim3(HID/32, HID/32), blk>>>(W1, W1tH, W1tL, HID, HID);
    tsplit_kernel<<<dim3(HID/32, HID/32), blk>>>(W2, W2tH, W2tL, HID, HID);
    tsplit_kernel<<<dim3((NKV*HD)/32, HID/32), blk>>>(Wk, WktH, WktL, HID, NKV*HD);
    tsplit_kernel<<<dim3((NKV*HD)/32, HID/32), blk>>>(Wv, WvtH, WvtL, HID, NKV*HD);
    tsplit_kernel<<<dim3(HID/32, HID/32), blk>>>(Wq, WqtH, WqtL, HID, HID);
    tsplit_kernel<<<dim3(HID/32, HID/32), blk>>>(Wd, WdtH, WdtL, HID, HID);

    // 1. Pl1 = relu(src @ W1 + b1)  (fp32 + split)
    bgemm_kernel<<<dim3(HID/128, MROWS/128), blk, SM_TOT>>>(
        srcH, srcL, W1tH, W1tL, b1, nullptr, pPl1, Pl1H, Pl1L,
        HID, M_RELU | M_WRITEC | M_SPLIT, 0);
    // 2. P = (Pl1 @ W2 + b2) + Pl1  (split only)
    bgemm_kernel<<<dim3(HID/128, MROWS/128), blk, SM_TOT>>>(
        Pl1H, Pl1L, W2tH, W2tL, b2, pPl1, nullptr, PH, PL,
        HID, M_RES | M_SPLIT, 0);
    // 3. K = P @ Wk + bk -> [B*NKV, S, HD]
    bgemm_kernel<<<dim3((NKV*HD)/128, MROWS/128), blk, SM_TOT>>>(
        PH, PL, WktH, WktL, bk, nullptr, pK, nullptr, nullptr,
        NKV*HD, M_SCATTER | M_WRITEC, NKV);
    // 4. V = P @ Wv + bv -> [B*NKV, S, HD]
    bgemm_kernel<<<dim3((NKV*HD)/128, MROWS/128), blk, SM_TOT>>>(
        PH, PL, WvtH, WvtL, bv, nullptr, pV, nullptr, nullptr,
        NKV*HD, M_SCATTER | M_WRITEC, NKV);
    // 5. Q = hidden @ Wq + bq -> [B*NH, S, HD]
    bgemm_kernel<<<dim3(HID/128, MROWS/128), blk, SM_TOT>>>(
        hidH, hidL, WqtH, WqtL, bq, nullptr, pQ, nullptr, nullptr,
        HID, M_SCATTER | M_WRITEC, NH);
    // 6. flash attention -> ctx split
    flash_kernel<<<dim3(SEQ/64, BATCH*NH), blk, fshmem>>>(pQ, pK, pV, ctxH, ctxL);
    // 7. pre = ctx @ Wd + bd
    bgemm_kernel<<<dim3(HID/128, MROWS/128), blk, SM_TOT>>>(
        ctxH, ctxL, WdtH, WdtL, bd, nullptr, pPre, nullptr, nullptr,
        HID, M_WRITEC, 0);
    // 8. out = layernorm(pre + hidden)
    ln_kernel<<<MROWS, 256>>>(pPre, hidden, gamma, beta, out);
}

// round 5
// speedup vs baseline: 2.9096x; 1.9562x over previous
#include <cuda_runtime.h>
#include <cuda_bf16.h>
#include <math.h>
#include <stdint.h>

// Problem constants (fixed shapes)
#define BATCH 2
#define SEQ   2048
#define HID   2048
#define NH    16
#define NKV   4
#define GRP   4
#define HD    128
#define MROWS (BATCH*SEQ)     // 4096
#define KDIM  2048

typedef __nv_bfloat16 bf16;

// ---------------- scratch (device globals) ----------------------------------
__device__ float g_Pl1[MROWS*HID];
__device__ float g_pre[MROWS*HID];

__device__ __align__(16) bf16 g_srcH[MROWS*HID], g_srcL[MROWS*HID];
__device__ __align__(16) bf16 g_hidH[MROWS*HID], g_hidL[MROWS*HID];
__device__ __align__(16) bf16 g_Pl1H[MROWS*HID], g_Pl1L[MROWS*HID];
__device__ __align__(16) bf16 g_PH  [MROWS*HID], g_PL  [MROWS*HID];
__device__ __align__(16) bf16 g_ctxH[MROWS*HID], g_ctxL[MROWS*HID];

__device__ __align__(16) bf16 g_QH [MROWS*HID],      g_QL [MROWS*HID];       // [B*NH][S][HD]
__device__ __align__(16) bf16 g_KH [MROWS*NKV*HD],   g_KL [MROWS*NKV*HD];    // [B*NKV][S][HD]
__device__ __align__(16) bf16 g_VtH[MROWS*NKV*HD],   g_VtL[MROWS*NKV*HD];    // [B*NKV][HD][S]

__device__ __align__(16) bf16 g_WqtH[HID*HID],      g_WqtL[HID*HID];
__device__ __align__(16) bf16 g_WktH[(NKV*HD)*HID], g_WktL[(NKV*HD)*HID];
__device__ __align__(16) bf16 g_WvtH[(NKV*HD)*HID], g_WvtL[(NKV*HD)*HID];
__device__ __align__(16) bf16 g_WdtH[HID*HID],      g_WdtL[HID*HID];
__device__ __align__(16) bf16 g_W1tH[HID*HID],      g_W1tL[HID*HID];
__device__ __align__(16) bf16 g_W2tH[HID*HID],      g_W2tL[HID*HID];

// ================= helpers ==================================================
__device__ __forceinline__ void mma_bf16(float (&d)[4],
                                         const uint32_t* a, const uint32_t* b) {
    asm volatile(
        "mma.sync.aligned.m16n8k16.row.col.f32.bf16.bf16.f32 "
        "{%0,%1,%2,%3}, {%4,%5,%6,%7}, {%8,%9}, {%0,%1,%2,%3};\n"
        : "+f"(d[0]), "+f"(d[1]), "+f"(d[2]), "+f"(d[3])
        : "r"(a[0]), "r"(a[1]), "r"(a[2]), "r"(a[3]), "r"(b[0]), "r"(b[1]));
}

__device__ __forceinline__ void ldsm4(uint32_t* r, uint32_t addr) {
    asm volatile("ldmatrix.sync.aligned.m8n8.x4.shared.b16 {%0,%1,%2,%3}, [%4];"
        : "=r"(r[0]), "=r"(r[1]), "=r"(r[2]), "=r"(r[3]) : "r"(addr));
}

__device__ __forceinline__ void cp16(uint32_t dst, const void* src) {
    asm volatile("cp.async.cg.shared.global [%0], [%1], 16;" :: "r"(dst), "l"(src));
}

__device__ __forceinline__ float ex2(float x) {
    float y; asm("ex2.approx.ftz.f32 %0, %1;" : "=f"(y) : "f"(x)); return y;
}

// split (v0,v1) into bf16 hi/lo packed words
__device__ __forceinline__ void split2(float v0, float v1,
                                       uint32_t& hi, uint32_t& lo) {
    __nv_bfloat162 h = __floats2bfloat162_rn(v0, v1);
    hi = *reinterpret_cast<uint32_t*>(&h);
    __nv_bfloat162 l = __floats2bfloat162_rn(v0 - __bfloat162float(h.x),
                                             v1 - __bfloat162float(h.y));
    lo = *reinterpret_cast<uint32_t*>(&l);
}

// ================= split kernels ============================================
__global__ __launch_bounds__(256)
void split_kernel(const float* __restrict__ x, bf16* __restrict__ hi,
                  bf16* __restrict__ lo, int n4)
{
    int i = blockIdx.x * blockDim.x + threadIdx.x;
    if (i >= n4) return;
    float4 v = ((const float4*)x)[i];
    uint32_t h0, l0, h1, l1;
    split2(v.x, v.y, h0, l0);
    split2(v.z, v.w, h1, l1);
    uint2 H = make_uint2(h0, h1), L = make_uint2(l0, l1);
    ((uint2*)hi)[i] = H;
    ((uint2*)lo)[i] = L;
}

// W [K][N] fp32 -> TH/TL [N][K] bf16
__global__ __launch_bounds__(256)
void tsplit_kernel(const float* __restrict__ W, bf16* __restrict__ TH,
                   bf16* __restrict__ TL, int Kd, int Nd)
{
    __shared__ float tl[32][33];
    int n0 = blockIdx.x * 32, k0 = blockIdx.y * 32;
    int tx = threadIdx.x & 31;
    int ty = threadIdx.x >> 5;
    #pragma unroll
    for (int i = 0; i < 4; i++)
        tl[ty + 8*i][tx] = W[(size_t)(k0 + ty + 8*i) * Nd + n0 + tx];
    __syncthreads();
    #pragma unroll
    for (int i = 0; i < 4; i++) {
        float v = tl[tx][ty + 8*i];
        bf16 h = __float2bfloat16(v);
        size_t o = (size_t)(n0 + ty + 8*i) * Kd + k0 + tx;
        TH[o] = h;
        TL[o] = __float2bfloat16(v - __bfloat162float(h));
    }
}

// ================= split-bf16 tensor GEMM ===================================
#define PITCHB 80
#define PLANE  10240
#define STAGEB 40960
#define SM_TOT (2*STAGEB)

#define M_RELU   1
#define M_RES    2
#define M_WRITEC 8
#define M_SPLIT  16
#define M_SCAT   32   // split + head scatter  [b*heads+head][s][d]
#define M_TSCAT  64   // split + V-transpose   [b*NKV+head][d][s]

__global__ __launch_bounds__(256)
void bgemm_kernel(const bf16* __restrict__ AH, const bf16* __restrict__ AL,
                  const bf16* __restrict__ BtH, const bf16* __restrict__ BtL,
                  const float* __restrict__ bias, const float* __restrict__ res,
                  float* __restrict__ C, bf16* __restrict__ CH, bf16* __restrict__ CL,
                  int N, int mode, int heads)
{
    extern __shared__ char smraw[];
    const uint32_t sbase = (uint32_t)__cvta_generic_to_shared(smraw);

    const int tid  = threadIdx.x;
    const int wid  = tid >> 5;
    const int lane = tid & 31;
    const int warpM = (wid & 1) * 64;
    const int warpN = (wid >> 1) * 32;
    const int mBase = blockIdx.y * 128;
    const int nBase = blockIdx.x * 128;

    const int lrow = tid >> 1;
    const int lcb  = (tid & 1) * 32;
    const size_t aOffG = (size_t)(mBase + lrow) * KDIM;
    const size_t bOffG = (size_t)(nBase + lrow) * KDIM;
    const uint32_t sRow = (uint32_t)(lrow * PITCHB + lcb);

    const int l15 = lane & 15;
    const int l16 = (lane >> 4) * 16;
    uint32_t aoff[4], boff[2];
    #pragma unroll
    for (int mi = 0; mi < 4; mi++)
        aoff[mi] = (uint32_t)((warpM + mi*16 + l15) * PITCHB + l16);
    #pragma unroll
    for (int n2 = 0; n2 < 2; n2++)
        boff[n2] = (uint32_t)((warpN + n2*16 + l15) * PITCHB + l16);

    float acc[4][4][4];
    #pragma unroll
    for (int i = 0; i < 4; i++)
        #pragma unroll
        for (int j = 0; j < 4; j++)
            #pragma unroll
            for (int c = 0; c < 4; c++) acc[i][j][c] = 0.f;

#define LOADSTAGE(kt, buf) do {                                                \
        uint32_t sb_ = sbase + (buf)*STAGEB + sRow;                            \
        const char* ga  = (const char*)(AH  + aOffG + (kt)*32) + lcb;          \
        const char* gal = (const char*)(AL  + aOffG + (kt)*32) + lcb;          \
        const char* gb  = (const char*)(BtH + bOffG + (kt)*32) + lcb;          \
        const char* gbl = (const char*)(BtL + bOffG + (kt)*32) + lcb;          \
        cp16(sb_,              ga);  cp16(sb_ + 16,            ga  + 16);      \
        cp16(sb_ +   PLANE,    gal); cp16(sb_ +   PLANE + 16,  gal + 16);      \
        cp16(sb_ + 2*PLANE,    gb);  cp16(sb_ + 2*PLANE + 16,  gb  + 16);      \
        cp16(sb_ + 3*PLANE,    gbl); cp16(sb_ + 3*PLANE + 16,  gbl + 16);      \
    } while (0)

    const int nk = KDIM / 32;
    LOADSTAGE(0, 0);
    asm volatile("cp.async.commit_group;" ::: "memory");

    for (int kt = 0; kt < nk; kt++) {
        const int buf = kt & 1;
        asm volatile("cp.async.wait_group 0;" ::: "memory");
        __syncthreads();
        if (kt + 1 < nk) {
            LOADSTAGE(kt + 1, buf ^ 1);
            asm volatile("cp.async.commit_group;" ::: "memory");
        }
        const uint32_t sb = sbase + buf * STAGEB;

        #pragma unroll
        for (int ks = 0; ks < 2; ks++) {
            const int kb = ks * 32;
            uint32_t ah[4][4], al[4][4], bh[4][2], bl[4][2];
            #pragma unroll
            for (int mi = 0; mi < 4; mi++) {
                ldsm4(ah[mi], sb + aoff[mi] + kb);
                ldsm4(al[mi], sb + PLANE + aoff[mi] + kb);
            }
            #pragma unroll
            for (int n2 = 0; n2 < 2; n2++) {
                uint32_t r[4];
                ldsm4(r, sb + 2*PLANE + boff[n2] + kb);
                bh[2*n2][0]   = r[0]; bh[2*n2][1]   = r[2];
                bh[2*n2+1][0] = r[1]; bh[2*n2+1][1] = r[3];
                ldsm4(r, sb + 3*PLANE + boff[n2] + kb);
                bl[2*n2][0]   = r[0]; bl[2*n2][1]   = r[2];
                bl[2*n2+1][0] = r[1]; bl[2*n2+1][1] = r[3];
            }
            #pragma unroll
            for (int mi = 0; mi < 4; mi++)
                #pragma unroll
                for (int ni = 0; ni < 4; ni++) {
                    mma_bf16(acc[mi][ni], al[mi], bh[ni]);
                    mma_bf16(acc[mi][ni], ah[mi], bl[ni]);
                    mma_bf16(acc[mi][ni], ah[mi], bh[ni]);
                }
        }
    }
#undef LOADSTAGE

    // -------- epilogue --------
    const int g  = lane >> 2;
    const int t4 = lane & 3;
    const int rw = mBase + warpM + g;
    const int cw = nBase + warpN + 2 * t4;
    #pragma unroll
    for (int mi = 0; mi < 4; mi++) {
        #pragma unroll
        for (int h = 0; h < 2; h++) {
            const int r = rw + mi * 16 + h * 8;
            const int b = r / SEQ, s = r - (r / SEQ) * SEQ;
            #pragma unroll
            for (int ni = 0; ni < 4; ni++) {
                const int c0 = cw + ni * 8;
                float v0 = acc[mi][ni][h*2 + 0] + bias[c0];
                float v1 = acc[mi][ni][h*2 + 1] + bias[c0 + 1];
                if (mode & M_RELU) { v0 = fmaxf(v0, 0.f); v1 = fmaxf(v1, 0.f); }
                if (mode & M_RES) {
                    v0 += res[(size_t)r * N + c0];
                    v1 += res[(size_t)r * N + c0 + 1];
                }
                if (mode & M_WRITEC) {
                    C[(size_t)r * N + c0]     = v0;
                    C[(size_t)r * N + c0 + 1] = v1;
                }
                if (mode & (M_SPLIT | M_SCAT | M_TSCAT)) {
                    uint32_t hi, lo;
                    split2(v0, v1, hi, lo);
                    if (mode & M_SPLIT) {
                        *(uint32_t*)(CH + (size_t)r * N + c0) = hi;
                        *(uint32_t*)(CL + (size_t)r * N + c0) = lo;
                    } else if (mode & M_SCAT) {
                        int head = c0 >> 7, d = c0 & 127;
                        size_t o = (((size_t)(b * heads + head)) * SEQ + s) * HD + d;
                        *(uint32_t*)(CH + o) = hi;
                        *(uint32_t*)(CL + o) = lo;
                    } else {
                        int head = c0 >> 7, d = c0 & 127;
                        size_t o = (((size_t)(b * NKV + head)) * HD + d) * SEQ + s;
                        __nv_bfloat162 H = *reinterpret_cast<__nv_bfloat162*>(&hi);
                        __nv_bfloat162 L = *reinterpret_cast<__nv_bfloat162*>(&lo);
                        CH[o]       = H.x;  CH[o + SEQ] = H.y;
                        CL[o]       = L.x;  CL[o + SEQ] = L.y;
                    }
                }
            }
        }
    }
}

// ================= tensor-core flash attention ==============================
// Q tile 128 rows, kv chunk 64, 8 warps (m16 each), split-bf16 3-term mma.
#define FQP 272                    // Q/K smem row pitch (128 bf16 + 16B pad)
#define FVP 144                    // Vt smem row pitch (64 bf16 + 16B pad)
#define FQ_BYTES (128*FQP)         // 34816 per plane
#define FK_BYTES (64*FQP)          // 17408 per plane
#define FV_BYTES (128*FVP)         // 18432 per plane
#define FK_STAGE (2*FK_BYTES)      // 34816
#define FV_STAGE (2*FV_BYTES)      // 36864
#define OFF_Q 0
#define OFF_K (2*FQ_BYTES)               // 69632
#define OFF_V (OFF_K + 2*FK_STAGE)       // 139264
#define FSMEM (OFF_V + 2*FV_STAGE)       // 212992

__global__ __launch_bounds__(256, 1)
void flash2_kernel(const bf16* __restrict__ QH, const bf16* __restrict__ QL,
                   const bf16* __restrict__ KH, const bf16* __restrict__ KL,
                   const bf16* __restrict__ VtH, const bf16* __restrict__ VtL,
                   bf16* __restrict__ ctxH, bf16* __restrict__ ctxL)
{
    extern __shared__ char smraw[];
    const uint32_t sb = (uint32_t)__cvta_generic_to_shared(smraw);

    const int tid  = threadIdx.x;
    const int wid  = tid >> 5;
    const int lane = tid & 31;
    const int g    = lane >> 2;
    const int t4   = lane & 3;
    const int l15  = lane & 15;
    const int l16  = (lane >> 4) * 16;

    const int qb = blockIdx.x;
    const int bh = blockIdx.y;
    const int b  = bh / NH;
    const int h  = bh % NH;
    const int kv = b * NKV + (h / GRP);

    const bf16* Qh  = QH  + ((size_t)bh * SEQ + qb * 128) * HD;
    const bf16* Ql  = QL  + ((size_t)bh * SEQ + qb * 128) * HD;
    const bf16* Kh  = KH  + (size_t)kv * SEQ * HD;
    const bf16* Kl  = KL  + (size_t)kv * SEQ * HD;
    const bf16* Vth = VtH + (size_t)kv * HD * SEQ;
    const bf16* Vtl = VtL + (size_t)kv * HD * SEQ;

    // ---- prologue loads: Q (both planes) + chunk 0 K/V ----
    #pragma unroll
    for (int j = 0; j < 8; j++) {                // Q: 2048 chunks/plane
        int idx = tid + j * 256;
        int r = idx >> 4, c = idx & 15;
        cp16(sb + OFF_Q + r * FQP + c * 16,            Qh + (size_t)r * HD + c * 8);
        cp16(sb + OFF_Q + FQ_BYTES + r * FQP + c * 16, Ql + (size_t)r * HD + c * 8);
    }
#define LOADKV(kc, st) do {                                                    \
        uint32_t kb_ = sb + OFF_K + (st) * FK_STAGE;                           \
        uint32_t vb_ = sb + OFF_V + (st) * FV_STAGE;                           \
        _Pragma("unroll")                                                      \
        for (int j = 0; j < 4; j++) {                                          \
            int idx = tid + j * 256;                                           \
            int r = idx >> 4, c = idx & 15;                                    \
            cp16(kb_ + r * FQP + c * 16,            Kh + (size_t)((kc) + r) * HD + c * 8); \
            cp16(kb_ + FK_BYTES + r * FQP + c * 16, Kl + (size_t)((kc) + r) * HD + c * 8); \
            int rv = idx >> 3, cv = idx & 7;                                   \
            cp16(vb_ + rv * FVP + cv * 16,            Vth + (size_t)rv * SEQ + (kc) + cv * 8); \
            cp16(vb_ + FV_BYTES + rv * FVP + cv * 16, Vtl + (size_t)rv * SEQ + (kc) + cv * 8); \
        }                                                                      \
    } while (0)

    LOADKV(0, 0);
    asm volatile("cp.async.commit_group;" ::: "memory");

    const int m0r = wid * 16;       // warp row base in q-tile
    float O[16][4];
    #pragma unroll
    for (int j = 0; j < 16; j++)
        #pragma unroll
        for (int c = 0; c < 4; c++) O[j][c] = 0.f;
    float mrow0 = -1e30f, mrow1 = -1e30f, lrow0 = 0.f, lrow1 = 0.f;
    const float c1 = 0.08838834764831845f * 1.4426950408889634f; // scale*log2e

    for (int ic = 0; ic < SEQ / 64; ic++) {
        const int buf = ic & 1;
        if (ic + 1 < SEQ / 64) {
            LOADKV((ic + 1) * 64, buf ^ 1);
            asm volatile("cp.async.commit_group;" ::: "memory");
            asm volatile("cp.async.wait_group 1;" ::: "memory");
        } else {
            asm volatile("cp.async.wait_group 0;" ::: "memory");
        }
        __syncthreads();

        // ---- scores: m16 x n64 over k=128 ----
        float s_[8][4];
        #pragma unroll
        for (int j = 0; j < 8; j++)
            #pragma unroll
            for (int c = 0; c < 4; c++) s_[j][c] = 0.f;

        const uint32_t kbase = sb + OFF_K + buf * FK_STAGE;
        #pragma unroll
        for (int kk = 0; kk < 8; kk++) {
            uint32_t aH[4], aL[4];
            uint32_t aoq = (uint32_t)((m0r + l15) * FQP + kk * 32 + l16);
            ldsm4(aH, sb + OFF_Q + aoq);
            ldsm4(aL, sb + OFF_Q + FQ_BYTES + aoq);
            #pragma unroll
            for (int j2 = 0; j2 < 4; j2++) {
                uint32_t bo = (uint32_t)((j2 * 16 + l15) * FQP + kk * 32 + l16);
                uint32_t rH[4], rL[4];
                ldsm4(rH, kbase + bo);
                ldsm4(rL, kbase + FK_BYTES + bo);
                uint32_t bh0[2] = { rH[0], rH[2] }, bh1[2] = { rH[1], rH[3] };
                uint32_t bl0[2] = { rL[0], rL[2] }, bl1[2] = { rL[1], rL[3] };
                mma_bf16(s_[2*j2],   aL, bh0);
                mma_bf16(s_[2*j2],   aH, bl0);
                mma_bf16(s_[2*j2],   aH, bh0);
                mma_bf16(s_[2*j2+1], aL, bh1);
                mma_bf16(s_[2*j2+1], aH, bl1);
                mma_bf16(s_[2*j2+1], aH, bh1);
            }
        }

        // ---- online softmax (rows g and g+8; quad = lanes sharing g) ----
        float zx0 = -1e30f, zx1 = -1e30f;
        #pragma unroll
        for (int j = 0; j < 8; j++) {
            zx0 = fmaxf(zx0, fmaxf(s_[j][0], s_[j][1]));
            zx1 = fmaxf(zx1, fmaxf(s_[j][2], s_[j][3]));
        }
        zx0 *= c1; zx1 *= c1;
        #pragma unroll
        for (int w = 1; w <= 2; w <<= 1) {
            zx0 = fmaxf(zx0, __shfl_xor_sync(0xffffffffu, zx0, w));
            zx1 = fmaxf(zx1, __shfl_xor_sync(0xffffffffu, zx1, w));
        }
        float mn0 = fmaxf(mrow0, zx0), mn1 = fmaxf(mrow1, zx1);
        float al0 = ex2(mrow0 - mn0),  al1 = ex2(mrow1 - mn1);
        float rs0 = 0.f, rs1 = 0.f;
        #pragma unroll
        for (int j = 0; j < 8; j++) {
            s_[j][0] = ex2(fmaf(s_[j][0], c1, -mn0));
            s_[j][1] = ex2(fmaf(s_[j][1], c1, -mn0));
            s_[j][2] = ex2(fmaf(s_[j][2], c1, -mn1));
            s_[j][3] = ex2(fmaf(s_[j][3], c1, -mn1));
            rs0 += s_[j][0] + s_[j][1];
            rs1 += s_[j][2] + s_[j][3];
        }
        #pragma unroll
        for (int w = 1; w <= 2; w <<= 1) {
            rs0 += __shfl_xor_sync(0xffffffffu, rs0, w);
            rs1 += __shfl_xor_sync(0xffffffffu, rs1, w);
        }
        lrow0 = lrow0 * al0 + rs0;
        lrow1 = lrow1 * al1 + rs1;
        mrow0 = mn0; mrow1 = mn1;

        #pragma unroll
        for (int j = 0; j < 16; j++) {
            O[j][0] *= al0; O[j][1] *= al0;
            O[j][2] *= al1; O[j][3] *= al1;
        }

        // ---- convert P to bf16 hi/lo A-fragments ----
        uint32_t ph[4][4], pl[4][4];
        #pragma unroll
        for (int kk = 0; kk < 4; kk++) {
            split2(s_[2*kk][0],   s_[2*kk][1],   ph[kk][0], pl[kk][0]);
            split2(s_[2*kk][2],   s_[2*kk][3],   ph[kk][1], pl[kk][1]);
            split2(s_[2*kk+1][0], s_[2*kk+1][1], ph[kk][2], pl[kk][2]);
            split2(s_[2*kk+1][2], s_[2*kk+1][3], ph[kk][3], pl[kk][3]);
        }

        // ---- O += P @ V  (m16 x n128 over k=64) ----
        const uint32_t vbase = sb + OFF_V + buf * FV_STAGE;
        #pragma unroll
        for (int kk = 0; kk < 4; kk++) {
            #pragma unroll
            for (int j2 = 0; j2 < 8; j2++) {
                uint32_t vo = (uint32_t)((j2 * 16 + l15) * FVP + kk * 32 + l16);
                uint32_t rH[4], rL[4];
                ldsm4(rH, vbase + vo);
                ldsm4(rL, vbase + FV_BYTES + vo);
                uint32_t bh0[2] = { rH[0], rH[2] }, bh1[2] = { rH[1], rH[3] };
                uint32_t bl0[2] = { rL[0], rL[2] }, bl1[2] = { rL[1], rL[3] };
                mma_bf16(O[2*j2],   pl[kk], bh0);
                mma_bf16(O[2*j2],   ph[kk], bl0);
                mma_bf16(O[2*j2],   ph[kk], bh0);
                mma_bf16(O[2*j2+1], pl[kk], bh1);
                mma_bf16(O[2*j2+1], ph[kk], bl1);
                mma_bf16(O[2*j2+1], ph[kk], bh1);
            }
        }
        __syncthreads();
    }
#undef LOADKV

    // ---- epilogue: normalize + split-write ctx ----
    const float inv0 = 1.f / lrow0, inv1 = 1.f / lrow1;
    const int q0 = qb * 128 + m0r + g;
    const int q1 = q0 + 8;
    const size_t base0 = ((size_t)(b * SEQ + q0)) * HID + h * HD;
    const size_t base1 = ((size_t)(b * SEQ + q1)) * HID + h * HD;
    #pragma unroll
    for (int j = 0; j < 16; j++) {
        const int col = j * 8 + 2 * t4;
        uint32_t hi, lo;
        split2(O[j][0] * inv0, O[j][1] * inv0, hi, lo);
        *(uint32_t*)(ctxH + base0 + col) = hi;
        *(uint32_t*)(ctxL + base0 + col) = lo;
        split2(O[j][2] * inv1, O[j][3] * inv1, hi, lo);
        *(uint32_t*)(ctxH + base1 + col) = hi;
        *(uint32_t*)(ctxL + base1 + col) = lo;
    }
}

// ---------------- residual + layernorm -------------------------------------
__device__ __forceinline__ float block_sum256(float v, float* sred)
{
    #pragma unroll
    for (int off = 16; off; off >>= 1) v += __shfl_xor_sync(0xffffffffu, v, off);
    int warp = threadIdx.x >> 5;
    if ((threadIdx.x & 31) == 0) sred[warp] = v;
    __syncthreads();
    if (threadIdx.x < 32) {
        float x = (threadIdx.x < 8) ? sred[threadIdx.x] : 0.f;
        #pragma unroll
        for (int off = 4; off; off >>= 1) x += __shfl_xor_sync(0xffffffffu, x, off);
        if (threadIdx.x == 0) sred[0] = x;
    }
    __syncthreads();
    float r = sred[0];
    __syncthreads();
    return r;
}

__global__ __launch_bounds__(256)
void ln_kernel(const float* __restrict__ x, const float* __restrict__ resid,
               const float* __restrict__ gamma, const float* __restrict__ beta,
               float* __restrict__ out)
{
    __shared__ float sred[32];
    const size_t row = blockIdx.x;
    const int tid = threadIdx.x;
    const float* xr = x     + row * HID;
    const float* rr = resid + row * HID;

    float v[8];
    float s = 0.f;
    #pragma unroll
    for (int t = 0; t < 8; t++) {
        int c = tid + t * 256;
        v[t] = xr[c] + rr[c];
        s += v[t];
    }
    float mean = block_sum256(s, sred) * (1.f / HID);

    float s2 = 0.f;
    #pragma unroll
    for (int t = 0; t < 8; t++) { float d = v[t] - mean; s2 += d * d; }
    float var = block_sum256(s2, sred) * (1.f / HID);
    float rstd = rsqrtf(var + 1e-12f);

    float* orow = out + row * HID;
    #pragma unroll
    for (int t = 0; t < 8; t++) {
        int c = tid + t * 256;
        orow[c] = (v[t] - mean) * rstd * gamma[c] + beta[c];
    }
}

// ---------------- launch ----------------------------------------------------
extern "C" void kernel_launch(void* const* d_in, const int* in_sizes, int n_in,
                              void* d_out, int out_size)
{
    const float* hidden = (const float*)d_in[0];
    const float* src    = (const float*)d_in[1];
    const float* Wq = (const float*)d_in[2];
    const float* bq = (const float*)d_in[3];
    const float* Wk = (const float*)d_in[4];
    const float* bk = (const float*)d_in[5];
    const float* Wv = (const float*)d_in[6];
    const float* bv = (const float*)d_in[7];
    const float* Wd = (const float*)d_in[8];
    const float* bd = (const float*)d_in[9];
    const float* W1 = (const float*)d_in[10];
    const float* b1 = (const float*)d_in[11];
    const float* W2 = (const float*)d_in[12];
    const float* b2 = (const float*)d_in[13];
    const float* gamma = (const float*)d_in[14];
    const float* beta  = (const float*)d_in[15];
    float* out = (float*)d_out;

    float *pPl1, *pPre;
    cudaGetSymbolAddress((void**)&pPl1, g_Pl1);
    cudaGetSymbolAddress((void**)&pPre, g_pre);

    bf16 *srcH,*srcL,*hidH,*hidL,*Pl1H,*Pl1L,*PH,*PL,*ctxH,*ctxL;
    bf16 *QH,*QL,*KHp,*KLp,*VtHp,*VtLp;
    cudaGetSymbolAddress((void**)&srcH, g_srcH); cudaGetSymbolAddress((void**)&srcL, g_srcL);
    cudaGetSymbolAddress((void**)&hidH, g_hidH); cudaGetSymbolAddress((void**)&hidL, g_hidL);
    cudaGetSymbolAddress((void**)&Pl1H, g_Pl1H); cudaGetSymbolAddress((void**)&Pl1L, g_Pl1L);
    cudaGetSymbolAddress((void**)&PH,   g_PH);   cudaGetSymbolAddress((void**)&PL,   g_PL);
    cudaGetSymbolAddress((void**)&ctxH, g_ctxH); cudaGetSymbolAddress((void**)&ctxL, g_ctxL);
    cudaGetSymbolAddress((void**)&QH,   g_QH);   cudaGetSymbolAddress((void**)&QL,   g_QL);
    cudaGetSymbolAddress((void**)&KHp,  g_KH);   cudaGetSymbolAddress((void**)&KLp,  g_KL);
    cudaGetSymbolAddress((void**)&VtHp, g_VtH);  cudaGetSymbolAddress((void**)&VtLp, g_VtL);

    bf16 *WqtH,*WqtL,*WktH,*WktL,*WvtH,*WvtL,*WdtH,*WdtL,*W1tH,*W1tL,*W2tH,*W2tL;
    cudaGetSymbolAddress((void**)&WqtH, g_WqtH); cudaGetSymbolAddress((void**)&WqtL, g_WqtL);
    cudaGetSymbolAddress((void**)&WktH, g_WktH); cudaGetSymbolAddress((void**)&WktL, g_WktL);
    cudaGetSymbolAddress((void**)&WvtH, g_WvtH); cudaGetSymbolAddress((void**)&WvtL, g_WvtL);
    cudaGetSymbolAddress((void**)&WdtH, g_WdtH); cudaGetSymbolAddress((void**)&WdtL, g_WdtL);
    cudaGetSymbolAddress((void**)&W1tH, g_W1tH); cudaGetSymbolAddress((void**)&W1tL, g_W1tL);
    cudaGetSymbolAddress((void**)&W2tH, g_W2tH); cudaGetSymbolAddress((void**)&W2tL, g_W2tL);

    cudaFuncSetAttribute(bgemm_kernel, cudaFuncAttributeMaxDynamicSharedMemorySize, SM_TOT);
    cudaFuncSetAttribute(flash2_kernel, cudaFuncAttributeMaxDynamicSharedMemorySize, FSMEM);

    dim3 blk(256);
    const int n4 = MROWS * HID / 4;

    split_kernel<<<n4/256, blk>>>(src,    srcH, srcL, n4);
    split_kernel<<<n4/256, blk>>>(hidden, hidH, hidL, n4);
    tsplit_kernel<<<dim3(HID/32, HID/32), blk>>>(W1, W1tH, W1tL, HID, HID);
    tsplit_kernel<<<dim3(HID/32, HID/32), blk>>>(W2, W2tH, W2tL, HID, HID);
    tsplit_kernel<<<dim3((NKV*HD)/32, HID/32), blk>>>(Wk, WktH, WktL, HID, NKV*HD);
    tsplit_kernel<<<dim3((NKV*HD)/32, HID/32), blk>>>(Wv, WvtH, WvtL, HID, NKV*HD);
    tsplit_kernel<<<dim3(HID/32, HID/32), blk>>>(Wq, WqtH, WqtL, HID, HID);
    tsplit_kernel<<<dim3(HID/32, HID/32), blk>>>(Wd, WdtH, WdtL, HID, HID);

    // 1. Pl1 = relu(src @ W1 + b1)
    bgemm_kernel<<<dim3(HID/128, MROWS/128), blk, SM_TOT>>>(
        srcH, srcL, W1tH, W1tL, b1, nullptr, pPl1, Pl1H, Pl1L,
        HID, M_RELU | M_WRITEC | M_SPLIT, 0);
    // 2. P = (Pl1 @ W2 + b2) + Pl1
    bgemm_kernel<<<dim3(HID/128, MROWS/128), blk, SM_TOT>>>(
        Pl1H, Pl1L, W2tH, W2tL, b2, pPl1, nullptr, PH, PL,
        HID, M_RES | M_SPLIT, 0);
    // 3. K -> [B*NKV][S][HD] bf16 hi/lo
    bgemm_kernel<<<dim3((NKV*HD)/128, MROWS/128), blk, SM_TOT>>>(
        PH, PL, WktH, WktL, bk, nullptr, nullptr, KHp, KLp,
        NKV*HD, M_SCAT, NKV);
    // 4. V -> [B*NKV][HD][S] bf16 hi/lo (transposed)
    bgemm_kernel<<<dim3((NKV*HD)/128, MROWS/128), blk, SM_TOT>>>(
        PH, PL, WvtH, WvtL, bv, nullptr, nullptr, VtHp, VtLp,
        NKV*HD, M_TSCAT, NKV);
    // 5. Q -> [B*NH][S][HD] bf16 hi/lo
    bgemm_kernel<<<dim3(HID/128, MROWS/128), blk, SM_TOT>>>(
        hidH, hidL, WqtH, WqtL, bq, nullptr, nullptr, QH, QL,
        HID, M_SCAT, NH);
    // 6. tensor-core flash attention
    flash2_kernel<<<dim3(SEQ/128, BATCH*NH), blk, FSMEM>>>(
        QH, QL, KHp, KLp, VtHp, VtLp, ctxH, ctxL);
    // 7. pre = ctx @ Wd + bd
    bgemm_kernel<<<dim3(HID/128, MROWS/128), blk, SM_TOT>>>(
        ctxH, ctxL, WdtH, WdtL, bd, nullptr, pPre, nullptr, nullptr,
        HID, M_WRITEC, 0);
    // 8. out = layernorm(pre + hidden)
    ln_kernel<<<MROWS, 256>>>(pPre, hidden, gamma, beta, out);
}

// round 7
// speedup vs baseline: 3.6594x; 1.2577x over previous
#include <cuda_runtime.h>
#include <cuda_bf16.h>
#include <math.h>
#include <stdint.h>

// Problem constants (fixed shapes)
#define BATCH 2
#define SEQ   2048
#define HID   2048
#define NH    16
#define NKV   4
#define GRP   4
#define HD    128
#define MROWS (BATCH*SEQ)     // 4096
#define KDIM  2048

typedef __nv_bfloat16 bf16;

// ---------------- scratch (device globals) ----------------------------------
__device__ float g_Pl1[MROWS*HID];
__device__ float g_pre[MROWS*HID];

// GEMM operands: TILED-SWIZZLED layout (see tiled_off)
__device__ __align__(16) bf16 g_srcH[MROWS*HID], g_srcL[MROWS*HID];
__device__ __align__(16) bf16 g_hidH[MROWS*HID], g_hidL[MROWS*HID];
__device__ __align__(16) bf16 g_Pl1H[MROWS*HID], g_Pl1L[MROWS*HID];
__device__ __align__(16) bf16 g_PH  [MROWS*HID], g_PL  [MROWS*HID];
__device__ __align__(16) bf16 g_ctxH[MROWS*HID], g_ctxL[MROWS*HID];

__device__ __align__(16) bf16 g_WqtH[HID*HID],      g_WqtL[HID*HID];
__device__ __align__(16) bf16 g_WktH[(NKV*HD)*HID], g_WktL[(NKV*HD)*HID];
__device__ __align__(16) bf16 g_WvtH[(NKV*HD)*HID], g_WvtL[(NKV*HD)*HID];
__device__ __align__(16) bf16 g_WdtH[HID*HID],      g_WdtL[HID*HID];
__device__ __align__(16) bf16 g_W1tH[HID*HID],      g_W1tL[HID*HID];
__device__ __align__(16) bf16 g_W2tH[HID*HID],      g_W2tL[HID*HID];

// flash operands: FLAT layout
__device__ __align__(16) bf16 g_QH [MROWS*HID],      g_QL [MROWS*HID];     // [B*NH][S][HD]
__device__ __align__(16) bf16 g_KH [MROWS*NKV*HD],   g_KL [MROWS*NKV*HD];  // [B*NKV][S][HD]
__device__ __align__(16) bf16 g_VtH[MROWS*NKV*HD],   g_VtL[MROWS*NKV*HD];  // [B*NKV][HD][S]

// ================= helpers ==================================================
__device__ __forceinline__ void mma_bf16(float (&d)[4],
                                         const uint32_t* a, const uint32_t* b) {
    asm volatile(
        "mma.sync.aligned.m16n8k16.row.col.f32.bf16.bf16.f32 "
        "{%0,%1,%2,%3}, {%4,%5,%6,%7}, {%8,%9}, {%0,%1,%2,%3};\n"
        : "+f"(d[0]), "+f"(d[1]), "+f"(d[2]), "+f"(d[3])
        : "r"(a[0]), "r"(a[1]), "r"(a[2]), "r"(a[3]), "r"(b[0]), "r"(b[1]));
}

__device__ __forceinline__ void ldsm4(uint32_t* r, uint32_t addr) {
    asm volatile("ldmatrix.sync.aligned.m8n8.x4.shared.b16 {%0,%1,%2,%3}, [%4];"
        : "=r"(r[0]), "=r"(r[1]), "=r"(r[2]), "=r"(r[3]) : "r"(addr));
}

__device__ __forceinline__ float ex2(float x) {
    float y; asm("ex2.approx.ftz.f32 %0, %1;" : "=f"(y) : "f"(x)); return y;
}

__device__ __forceinline__ void split2(float v0, float v1,
                                       uint32_t& hi, uint32_t& lo) {
    __nv_bfloat162 h = __floats2bfloat162_rn(v0, v1);
    hi = *reinterpret_cast<uint32_t*>(&h);
    __nv_bfloat162 l = __floats2bfloat162_rn(v0 - __bfloat162float(h.x),
                                             v1 - __bfloat162float(h.y));
    lo = *reinterpret_cast<uint32_t*>(&l);
}

__device__ __forceinline__ uint32_t smem_u32(const void* p) {
    uint32_t a;
    asm("{ .reg .u64 t; cvta.to.shared.u64 t, %1; cvt.u32.u64 %0, t; }"
        : "=r"(a) : "l"(p));
    return a;
}

// bulk async copy global->shared with mbarrier tx accounting
__device__ __forceinline__ void bulkcp(uint32_t dst, const void* src,
                                       uint32_t bytes, uint32_t mbar) {
    asm volatile(
        "cp.async.bulk.shared::cluster.global.mbarrier::complete_tx::bytes "
        "[%0], [%1], %2, [%3];"
        :: "r"(dst), "l"(src), "r"(bytes), "r"(mbar) : "memory");
}

#define MBAR_INIT(mbar, cnt) \
    asm volatile("mbarrier.init.shared.b64 [%0], %1;" \
                 :: "r"((uint32_t)(mbar)), "r"((uint32_t)(cnt)) : "memory")
#define MBAR_EXPECT(mbar, bytes) \
    asm volatile("mbarrier.arrive.expect_tx.shared.b64 _, [%0], %1;" \
                 :: "r"((uint32_t)(mbar)), "r"((uint32_t)(bytes)) : "memory")

#define MBAR_WAIT(mbar, par) do {                                              \
    uint32_t _m = (uint32_t)(mbar), _p = (uint32_t)(par), _d;                  \
    asm volatile("{\n\t.reg .pred p;\n\t"                                      \
        "mbarrier.try_wait.parity.acquire.cta.shared::cta.b64 p, [%1], %2;\n\t"\
        "selp.b32 %0, 1, 0, p;\n\t}" : "=r"(_d) : "r"(_m), "r"(_p) : "memory");\
    if (!_d) {                                                                 \
        asm volatile("{\n\t.reg .pred P1;\n\t"                                 \
            "WL_%=:\n\t"                                                       \
            "mbarrier.try_wait.parity.acquire.cta.shared::cta.b64 P1, [%0], %1, 0x989680;\n\t" \
            "@P1 bra.uni WD_%=;\n\t"                                           \
            "bra.uni WL_%=;\n\t"                                               \
            "WD_%=:\n\t}" :: "r"(_m), "r"(_p) : "memory");                     \
    } } while (0)

// ---- tiled-swizzled GEMM operand layout -------------------------------------
// 128-row x 64-col (bf16) blocks, 16384 B each, blocks row-major in (mb, kb).
// Within a block: row ri (0..127) at ri*128; 16B chunk ci stored at (ci^(ri&7)).
__device__ __forceinline__ size_t tiled_off(int r, int kchunk, int Kd) {
    int mb = r >> 7, kb = kchunk >> 3;
    int ri = r & 127, ci = kchunk & 7;
    int cs = ci ^ (ri & 7);
    return ((size_t)(mb * (Kd >> 6) + kb)) * 16384 + ri * 128 + cs * 16;
}

// ================= split kernels (write tiled layout) ========================
// one thread = one 16B chunk (8 fp32 in -> 16B hi + 16B lo out). Kd = 2048.
__global__ __launch_bounds__(256)
void split_kernel(const float* __restrict__ x, bf16* __restrict__ hi,
                  bf16* __restrict__ lo, int n8)
{
    int i = blockIdx.x * blockDim.x + threadIdx.x;
    if (i >= n8) return;
    int r  = i >> 8;        // 2048/8 = 256 chunks per row
    int kc = i & 255;
    const float4* xp = (const float4*)x + (size_t)i * 2;
    float4 v0 = xp[0], v1 = xp[1];
    uint32_t h0,l0,h1,l1,h2,l2,h3,l3;
    split2(v0.x, v0.y, h0, l0); split2(v0.z, v0.w, h1, l1);
    split2(v1.x, v1.y, h2, l2); split2(v1.z, v1.w, h3, l3);
    size_t o = tiled_off(r, kc, 2048);
    *(uint4*)((char*)hi + o) = make_uint4(h0, h1, h2, h3);
    *(uint4*)((char*)lo + o) = make_uint4(l0, l1, l2, l3);
}

// W [K][N] fp32 -> TH/TL tiled [N][K] bf16 (transpose + split + tile-swizzle)
__global__ __launch_bounds__(256)
void tsplit_kernel(const float* __restrict__ W, bf16* __restrict__ TH,
                   bf16* __restrict__ TL, int Kd, int Nd)
{
    __shared__ float tl[32][33];
    int n0 = blockIdx.x * 32, k0 = blockIdx.y * 32;
    int tx = threadIdx.x & 31;
    int ty = threadIdx.x >> 5;
    #pragma unroll
    for (int i = 0; i < 4; i++)
        tl[ty + 8*i][tx] = W[(size_t)(k0 + ty + 8*i) * Nd + n0 + tx];
    __syncthreads();
    #pragma unroll
    for (int i = 0; i < 4; i++) {
        float v = tl[tx][ty + 8*i];
        bf16 h = __float2bfloat16(v);
        int n_ = n0 + ty + 8*i, k_ = k0 + tx;
        size_t o = tiled_off(n_, k_ >> 3, 2048) + (size_t)(k_ & 7) * 2;
        *(bf16*)((char*)TH + o) = h;
        *(bf16*)((char*)TL + o) = __float2bfloat16(v - __bfloat162float(h));
    }
}

// ================= bulk-load split-bf16 tensor GEMM =========================
// Tile 128x128, ktile 64, 8 warps (m64 x n32), 2-stage bulk pipeline.
// Per stage: 4 bulk copies of one 16KB tiled block each (AH, AL, BH, BL).
#define TPL   16384
#define TSTG  (4*TPL)                 // 65536
#define TC_SMEM (64 + 2*TSTG)         // 131136

#define M_RELU   1
#define M_RES    2
#define M_WRITEC 8
#define M_SPLIT  16
#define M_SCAT   32
#define M_TSCAT  64

__global__ __launch_bounds__(256)
void bgemm_kernel(const bf16* __restrict__ AH, const bf16* __restrict__ AL,
                  const bf16* __restrict__ BtH, const bf16* __restrict__ BtL,
                  const float* __restrict__ bias, const float* __restrict__ res,
                  float* __restrict__ C, bf16* __restrict__ CH, bf16* __restrict__ CL,
                  int N, int mode, int heads)
{
    extern __shared__ char smraw[];
    const uint32_t sb  = smem_u32(smraw);
    const uint32_t mb0 = sb;            // two mbarriers at [0,8),[8,16)
    const uint32_t sb0 = sb + 64;

    const int tid  = threadIdx.x;
    const int wid  = tid >> 5;
    const int lane = tid & 31;
    const int l15  = lane & 15;
    const int lsel = lane >> 4;         // 0/1: second 16B half
    const int warpM = (wid & 1) * 64;
    const int warpN = (wid >> 1) * 32;
    const int mBase = blockIdx.y * 128;
    const int nBase = blockIdx.x * 128;

    if (tid == 0) { MBAR_INIT(mb0, 1); MBAR_INIT(mb0 + 8, 1); }
    __syncthreads();

    float acc[4][4][4];
    #pragma unroll
    for (int i = 0; i < 4; i++)
        #pragma unroll
        for (int j = 0; j < 4; j++)
            #pragma unroll
            for (int c = 0; c < 4; c++) acc[i][j][c] = 0.f;

#define TLOAD(kt, bf_) do { if (tid == 0) {                                    \
        MBAR_EXPECT(mb0 + (bf_)*8, (uint32_t)TSTG);                            \
        uint32_t st_ = sb0 + (bf_)*TSTG;                                       \
        size_t ao_ = ((size_t)(blockIdx.y * 32 + (kt))) * TPL;                 \
        size_t bo_ = ((size_t)(blockIdx.x * 32 + (kt))) * TPL;                 \
        bulkcp(st_,           (const char*)AH  + ao_, TPL, mb0 + (bf_)*8);     \
        bulkcp(st_ +   TPL,   (const char*)AL  + ao_, TPL, mb0 + (bf_)*8);     \
        bulkcp(st_ + 2*TPL,   (const char*)BtH + bo_, TPL, mb0 + (bf_)*8);     \
        bulkcp(st_ + 3*TPL,   (const char*)BtL + bo_, TPL, mb0 + (bf_)*8);     \
    } } while (0)

    const int nk = KDIM / 64;        // 32 stages
    TLOAD(0, 0);

    for (int kt = 0; kt < nk; kt++) {
        const int buf = kt & 1;
        if (kt + 1 < nk) TLOAD(kt + 1, buf ^ 1);
        MBAR_WAIT(mb0 + buf * 8, (kt >> 1) & 1);
        const uint32_t st = sb0 + buf * TSTG;

        #pragma unroll
        for (int ks = 0; ks < 4; ks++) {
            uint32_t ah[4][4], al[4][4], bh[4][2], bl[4][2];
            #pragma unroll
            for (int mi = 0; mi < 4; mi++) {
                int ar = warpM + mi * 16 + l15;
                uint32_t ad = st + ar * 128 + (((ks * 2 + lsel) ^ (ar & 7)) << 4);
                ldsm4(ah[mi], ad);
                ldsm4(al[mi], ad + TPL);
            }
            #pragma unroll
            for (int n2 = 0; n2 < 2; n2++) {
                int br = warpN + n2 * 16 + l15;
                uint32_t bd = st + 2*TPL + br * 128
                            + (((ks * 2 + lsel) ^ (br & 7)) << 4);
                uint32_t r[4];
                ldsm4(r, bd);
                bh[2*n2][0]   = r[0]; bh[2*n2][1]   = r[2];
                bh[2*n2+1][0] = r[1]; bh[2*n2+1][1] = r[3];
                ldsm4(r, bd + TPL);
                bl[2*n2][0]   = r[0]; bl[2*n2][1]   = r[2];
                bl[2*n2+1][0] = r[1]; bl[2*n2+1][1] = r[3];
            }
            #pragma unroll
            for (int mi = 0; mi < 4; mi++)
                #pragma unroll
                for (int ni = 0; ni < 4; ni++) {
                    mma_bf16(acc[mi][ni], al[mi], bh[ni]);
                    mma_bf16(acc[mi][ni], ah[mi], bl[ni]);
                    mma_bf16(acc[mi][ni], ah[mi], bh[ni]);
                }
        }
        __syncthreads();   // all reads of buf done before it is refilled
    }
#undef TLOAD

    // -------- epilogue --------
    const int g  = lane >> 2;
    const int t4 = lane & 3;
    const int rw = mBase + warpM + g;
    const int cw = nBase + warpN + 2 * t4;
    #pragma unroll
    for (int mi = 0; mi < 4; mi++) {
        #pragma unroll
        for (int h = 0; h < 2; h++) {
            const int r = rw + mi * 16 + h * 8;
            const int b = r / SEQ, s = r - (r / SEQ) * SEQ;
            #pragma unroll
            for (int ni = 0; ni < 4; ni++) {
                const int c0 = cw + ni * 8;
                float v0 = acc[mi][ni][h*2 + 0] + bias[c0];
                float v1 = acc[mi][ni][h*2 + 1] + bias[c0 + 1];
                if (mode & M_RELU) { v0 = fmaxf(v0, 0.f); v1 = fmaxf(v1, 0.f); }
                if (mode & M_RES) {
                    v0 += res[(size_t)r * N + c0];
                    v1 += res[(size_t)r * N + c0 + 1];
                }
                if (mode & M_WRITEC) {
                    C[(size_t)r * N + c0]     = v0;
                    C[(size_t)r * N + c0 + 1] = v1;
                }
                if (mode & (M_SPLIT | M_SCAT | M_TSCAT)) {
                    uint32_t hi, lo;
                    split2(v0, v1, hi, lo);
                    if (mode & M_SPLIT) {
                        size_t o = tiled_off(r, c0 >> 3, 2048)
                                 + (size_t)(c0 & 7) * 2;
                        *(uint32_t*)((char*)CH + o) = hi;
                        *(uint32_t*)((char*)CL + o) = lo;
                    } else if (mode & M_SCAT) {
                        int head = c0 >> 7, d = c0 & 127;
                        size_t o = (((size_t)(b * heads + head)) * SEQ + s) * HD + d;
                        *(uint32_t*)(CH + o) = hi;
                        *(uint32_t*)(CL + o) = lo;
                    } else {
                        int head = c0 >> 7, d = c0 & 127;
                        size_t o = (((size_t)(b * NKV + head)) * HD + d) * SEQ + s;
                        __nv_bfloat162 H = *reinterpret_cast<__nv_bfloat162*>(&hi);
                        __nv_bfloat162 L = *reinterpret_cast<__nv_bfloat162*>(&lo);
                        CH[o] = H.x;  CH[o + SEQ] = H.y;
                        CL[o] = L.x;  CL[o + SEQ] = L.y;
                    }
                }
            }
        }
    }
}

// ================= tensor-core flash attention (bulk loads) =================
#define FQP 272
#define FVP 144
#define FQ_BYTES (128*FQP)
#define FK_BYTES (64*FQP)
#define FV_BYTES (128*FVP)
#define FK_STAGE (2*FK_BYTES)
#define FV_STAGE (2*FV_BYTES)
#define OFF_Q 0
#define OFF_K (2*FQ_BYTES)
#define OFF_V (OFF_K + 2*FK_STAGE)
#define OFF_MB (OFF_V + 2*FV_STAGE)     // 212992: two mbarriers
#define FSMEM (OFF_MB + 64)

__global__ __launch_bounds__(256, 1)
void flash2_kernel(const bf16* __restrict__ QH, const bf16* __restrict__ QL,
                   const bf16* __restrict__ KH, const bf16* __restrict__ KL,
                   const bf16* __restrict__ VtH, const bf16* __restrict__ VtL,
                   bf16* __restrict__ ctxH, bf16* __restrict__ ctxL)
{
    extern __shared__ char smraw[];
    const uint32_t sb  = smem_u32(smraw);
    const uint32_t fmb = sb + OFF_MB;

    const int tid  = threadIdx.x;
    const int wid  = tid >> 5;
    const int lane = tid & 31;
    const int g    = lane >> 2;
    const int t4   = lane & 3;
    const int l15  = lane & 15;
    const int l16  = (lane >> 4) * 16;

    const int qb = blockIdx.x;
    const int bh = blockIdx.y;
    const int b  = bh / NH;
    const int h  = bh % NH;
    const int kv = b * NKV + (h / GRP);

    const bf16* Qh  = QH  + ((size_t)bh * SEQ + qb * 128) * HD;
    const bf16* Ql  = QL  + ((size_t)bh * SEQ + qb * 128) * HD;
    const bf16* Kh  = KH  + (size_t)kv * SEQ * HD;
    const bf16* Kl  = KL  + (size_t)kv * SEQ * HD;
    const bf16* Vth = VtH + (size_t)kv * HD * SEQ;
    const bf16* Vtl = VtL + (size_t)kv * HD * SEQ;

    if (tid == 0) { MBAR_INIT(fmb, 1); MBAR_INIT(fmb + 8, 1); }
    __syncthreads();

// K/V bulks for one chunk into stage st (no expect)
#define KVB(kc, st) do {                                                       \
        for (int o = tid; o < 384; o += 256) {                                 \
            if (o < 128) {                                                     \
                int pl = o >> 6, rr = o & 63;                                  \
                bulkcp(sb + OFF_K + (st)*FK_STAGE + pl*FK_BYTES + rr*FQP,      \
                       (pl ? Kl : Kh) + (size_t)((kc) + rr) * HD, 256,         \
                       fmb + (st)*8);                                          \
            } else {                                                           \
                int q_ = o - 128; int pl = q_ >> 7, rv = q_ & 127;             \
                bulkcp(sb + OFF_V + (st)*FV_STAGE + pl*FV_BYTES + rv*FVP,      \
                       (pl ? Vtl : Vth) + (size_t)rv * SEQ + (kc), 128,        \
                       fmb + (st)*8);                                          \
            } } } while (0)

#define LOADKV(kc, st) do {                                                    \
        if (tid == 0) MBAR_EXPECT(fmb + (st)*8, 65536);                        \
        KVB(kc, st); } while (0)

    // prologue: Q (65536 B) + chunk0 K/V (65536 B) on stage-0 barrier
    if (tid == 0) MBAR_EXPECT(fmb, 131072);
    {
        int pl = tid >> 7, rq = tid & 127;
        bulkcp(sb + OFF_Q + pl * FQ_BYTES + rq * FQP,
               (pl ? Ql : Qh) + (size_t)rq * HD, 256, fmb);
    }
    KVB(0, 0);

    const int m0r = wid * 16;
    float O[16][4];
    #pragma unroll
    for (int j = 0; j < 16; j++)
        #pragma unroll
        for (int c = 0; c < 4; c++) O[j][c] = 0.f;
    float mrow0 = -1e30f, mrow1 = -1e30f, lrow0 = 0.f, lrow1 = 0.f;
    const float c1 = 0.08838834764831845f * 1.4426950408889634f;

    for (int ic = 0; ic < SEQ / 64; ic++) {
        const int buf = ic & 1;
        if (ic + 1 < SEQ / 64) LOADKV((ic + 1) * 64, buf ^ 1);
        MBAR_WAIT(fmb + buf * 8, (ic >> 1) & 1);

        float s_[8][4];
        #pragma unroll
        for (int j = 0; j < 8; j++)
            #pragma unroll
            for (int c = 0; c < 4; c++) s_[j][c] = 0.f;

        const uint32_t kbase = sb + OFF_K + buf * FK_STAGE;
        #pragma unroll
        for (int kk = 0; kk < 8; kk++) {
            uint32_t aH[4], aL[4];
            uint32_t aoq = (uint32_t)((m0r + l15) * FQP + kk * 32 + l16);
            ldsm4(aH, sb + OFF_Q + aoq);
            ldsm4(aL, sb + OFF_Q + FQ_BYTES + aoq);
            #pragma unroll
            for (int j2 = 0; j2 < 4; j2++) {
                uint32_t bo = (uint32_t)((j2 * 16 + l15) * FQP + kk * 32 + l16);
                uint32_t rH[4], rL[4];
                ldsm4(rH, kbase + bo);
                ldsm4(rL, kbase + FK_BYTES + bo);
                uint32_t bh0[2] = { rH[0], rH[2] }, bh1[2] = { rH[1], rH[3] };
                uint32_t bl0[2] = { rL[0], rL[2] }, bl1[2] = { rL[1], rL[3] };
                mma_bf16(s_[2*j2],   aL, bh0);
                mma_bf16(s_[2*j2],   aH, bl0);
                mma_bf16(s_[2*j2],   aH, bh0);
                mma_bf16(s_[2*j2+1], aL, bh1);
                mma_bf16(s_[2*j2+1], aH, bl1);
                mma_bf16(s_[2*j2+1], aH, bh1);
            }
        }

        float zx0 = -1e30f, zx1 = -1e30f;
        #pragma unroll
        for (int j = 0; j < 8; j++) {
            zx0 = fmaxf(zx0, fmaxf(s_[j][0], s_[j][1]));
            zx1 = fmaxf(zx1, fmaxf(s_[j][2], s_[j][3]));
        }
        zx0 *= c1; zx1 *= c1;
        #pragma unroll
        for (int w = 1; w <= 2; w <<= 1) {
            zx0 = fmaxf(zx0, __shfl_xor_sync(0xffffffffu, zx0, w));
            zx1 = fmaxf(zx1, __shfl_xor_sync(0xffffffffu, zx1, w));
        }
        float mn0 = fmaxf(mrow0, zx0), mn1 = fmaxf(mrow1, zx1);
        float al0 = ex2(mrow0 - mn0),  al1 = ex2(mrow1 - mn1);
        float rs0 = 0.f, rs1 = 0.f;
        #pragma unroll
        for (int j = 0; j < 8; j++) {
            s_[j][0] = ex2(fmaf(s_[j][0], c1, -mn0));
            s_[j][1] = ex2(fmaf(s_[j][1], c1, -mn0));
            s_[j][2] = ex2(fmaf(s_[j][2], c1, -mn1));
            s_[j][3] = ex2(fmaf(s_[j][3], c1, -mn1));
            rs0 += s_[j][0] + s_[j][1];
            rs1 += s_[j][2] + s_[j][3];
        }
        #pragma unroll
        for (int w = 1; w <= 2; w <<= 1) {
            rs0 += __shfl_xor_sync(0xffffffffu, rs0, w);
            rs1 += __shfl_xor_sync(0xffffffffu, rs1, w);
        }
        lrow0 = lrow0 * al0 + rs0;
        lrow1 = lrow1 * al1 + rs1;
        mrow0 = mn0; mrow1 = mn1;

        #pragma unroll
        for (int j = 0; j < 16; j++) {
            O[j][0] *= al0; O[j][1] *= al0;
            O[j][2] *= al1; O[j][3] *= al1;
        }

        uint32_t ph[4][4], pl[4][4];
        #pragma unroll
        for (int kk = 0; kk < 4; kk++) {
            split2(s_[2*kk][0],   s_[2*kk][1],   ph[kk][0], pl[kk][0]);
            split2(s_[2*kk][2],   s_[2*kk][3],   ph[kk][1], pl[kk][1]);
            split2(s_[2*kk+1][0], s_[2*kk+1][1], ph[kk][2], pl[kk][2]);
            split2(s_[2*kk+1][2], s_[2*kk+1][3], ph[kk][3], pl[kk][3]);
        }

        const uint32_t vbase = sb + OFF_V + buf * FV_STAGE;
        #pragma unroll
        for (int kk = 0; kk < 4; kk++) {
            #pragma unroll
            for (int j2 = 0; j2 < 8; j2++) {
                uint32_t vo = (uint32_t)((j2 * 16 + l15) * FVP + kk * 32 + l16);
                uint32_t rH[4], rL[4];
                ldsm4(rH, vbase + vo);
                ldsm4(rL, vbase + FV_BYTES + vo);
                uint32_t bh0[2] = { rH[0], rH[2] }, bh1[2] = { rH[1], rH[3] };
                uint32_t bl0[2] = { rL[0], rL[2] }, bl1[2] = { rL[1], rL[3] };
                mma_bf16(O[2*j2],   pl[kk], bh0);
                mma_bf16(O[2*j2],   ph[kk], bl0);
                mma_bf16(O[2*j2],   ph[kk], bh0);
                mma_bf16(O[2*j2+1], pl[kk], bh1);
                mma_bf16(O[2*j2+1], ph[kk], bl1);
                mma_bf16(O[2*j2+1], ph[kk], bh1);
            }
        }
        __syncthreads();   // buf reads done before refill at ic+1
    }
#undef LOADKV
#undef KVB

    // ---- epilogue: normalize + tiled split-write ctx ----
    const float inv0 = 1.f / lrow0, inv1 = 1.f / lrow1;
    const int q0 = qb * 128 + m0r + g;
    const int q1 = q0 + 8;
    const int row0 = b * SEQ + q0;
    const int row1 = b * SEQ + q1;
    #pragma unroll
    for (int j = 0; j < 16; j++) {
        const int colg = h * HD + j * 8 + 2 * t4;
        uint32_t hi, lo;
        split2(O[j][0] * inv0, O[j][1] * inv0, hi, lo);
        size_t o0 = tiled_off(row0, colg >> 3, 2048) + (size_t)(colg & 7) * 2;
        *(uint32_t*)((char*)ctxH + o0) = hi;
        *(uint32_t*)((char*)ctxL + o0) = lo;
        split2(O[j][2] * inv1, O[j][3] * inv1, hi, lo);
        size_t o1 = tiled_off(row1, colg >> 3, 2048) + (size_t)(colg & 7) * 2;
        *(uint32_t*)((char*)ctxH + o1) = hi;
        *(uint32_t*)((char*)ctxL + o1) = lo;
    }
}

// ---------------- residual + layernorm -------------------------------------
__device__ __forceinline__ float block_sum256(float v, float* sred)
{
    #pragma unroll
    for (int off = 16; off; off >>= 1) v += __shfl_xor_sync(0xffffffffu, v, off);
    int warp = threadIdx.x >> 5;
    if ((threadIdx.x & 31) == 0) sred[warp] = v;
    __syncthreads();
    if (threadIdx.x < 32) {
        float x = (threadIdx.x < 8) ? sred[threadIdx.x] : 0.f;
        #pragma unroll
        for (int off = 4; off; off >>= 1) x += __shfl_xor_sync(0xffffffffu, x, off);
        if (threadIdx.x == 0) sred[0] = x;
    }
    __syncthreads();
    float r = sred[0];
    __syncthreads();
    return r;
}

__global__ __launch_bounds__(256)
void ln_kernel(const float* __restrict__ x, const float* __restrict__ resid,
               const float* __restrict__ gamma, const float* __restrict__ beta,
               float* __restrict__ out)
{
    __shared__ float sred[32];
    const size_t row = blockIdx.x;
    const int tid = threadIdx.x;
    const float* xr = x     + row * HID;
    const float* rr = resid + row * HID;

    float v[8];
    float s = 0.f;
    #pragma unroll
    for (int t = 0; t < 8; t++) {
        int c = tid + t * 256;
        v[t] = xr[c] + rr[c];
        s += v[t];
    }
    float mean = block_sum256(s, sred) * (1.f / HID);

    float s2 = 0.f;
    #pragma unroll
    for (int t = 0; t < 8; t++) { float d = v[t] - mean; s2 += d * d; }
    float var = block_sum256(s2, sred) * (1.f / HID);
    float rstd = rsqrtf(var + 1e-12f);

    float* orow = out + row * HID;
    #pragma unroll
    for (int t = 0; t < 8; t++) {
        int c = tid + t * 256;
        orow[c] = (v[t] - mean) * rstd * gamma[c] + beta[c];
    }
}

// ---------------- launch ----------------------------------------------------
extern "C" void kernel_launch(void* const* d_in, const int* in_sizes, int n_in,
                              void* d_out, int out_size)
{
    const float* hidden = (const float*)d_in[0];
    const float* src    = (const float*)d_in[1];
    const float* Wq = (const float*)d_in[2];
    const float* bq = (const float*)d_in[3];
    const float* Wk = (const float*)d_in[4];
    const float* bk = (const float*)d_in[5];
    const float* Wv = (const float*)d_in[6];
    const float* bv = (const float*)d_in[7];
    const float* Wd = (const float*)d_in[8];
    const float* bd = (const float*)d_in[9];
    const float* W1 = (const float*)d_in[10];
    const float* b1 = (const float*)d_in[11];
    const float* W2 = (const float*)d_in[12];
    const float* b2 = (const float*)d_in[13];
    const float* gamma = (const float*)d_in[14];
    const float* beta  = (const float*)d_in[15];
    float* out = (float*)d_out;

    float *pPl1, *pPre;
    cudaGetSymbolAddress((void**)&pPl1, g_Pl1);
    cudaGetSymbolAddress((void**)&pPre, g_pre);

    bf16 *srcH,*srcL,*hidH,*hidL,*Pl1H,*Pl1L,*PH,*PL,*ctxH,*ctxL;
    bf16 *QH,*QL,*KHp,*KLp,*VtHp,*VtLp;
    cudaGetSymbolAddress((void**)&srcH, g_srcH); cudaGetSymbolAddress((void**)&srcL, g_srcL);
    cudaGetSymbolAddress((void**)&hidH, g_hidH); cudaGetSymbolAddress((void**)&hidL, g_hidL);
    cudaGetSymbolAddress((void**)&Pl1H, g_Pl1H); cudaGetSymbolAddress((void**)&Pl1L, g_Pl1L);
    cudaGetSymbolAddress((void**)&PH,   g_PH);   cudaGetSymbolAddress((void**)&PL,   g_PL);
    cudaGetSymbolAddress((void**)&ctxH, g_ctxH); cudaGetSymbolAddress((void**)&ctxL, g_ctxL);
    cudaGetSymbolAddress((void**)&QH,   g_QH);   cudaGetSymbolAddress((void**)&QL,   g_QL);
    cudaGetSymbolAddress((void**)&KHp,  g_KH);   cudaGetSymbolAddress((void**)&KLp,  g_KL);
    cudaGetSymbolAddress((void**)&VtHp, g_VtH);  cudaGetSymbolAddress((void**)&VtLp, g_VtL);

    bf16 *WqtH,*WqtL,*WktH,*WktL,*WvtH,*WvtL,*WdtH,*WdtL,*W1tH,*W1tL,*W2tH,*W2tL;
    cudaGetSymbolAddress((void**)&WqtH, g_WqtH); cudaGetSymbolAddress((void**)&WqtL, g_WqtL);
    cudaGetSymbolAddress((void**)&WktH, g_WktH); cudaGetSymbolAddress((void**)&WktL, g_WktL);
    cudaGetSymbolAddress((void**)&WvtH, g_WvtH); cudaGetSymbolAddress((void**)&WvtL, g_WvtL);
    cudaGetSymbolAddress((void**)&WdtH, g_WdtH); cudaGetSymbolAddress((void**)&WdtL, g_WdtL);
    cudaGetSymbolAddress((void**)&W1tH, g_W1tH); cudaGetSymbolAddress((void**)&W1tL, g_W1tL);
    cudaGetSymbolAddress((void**)&W2tH, g_W2tH); cudaGetSymbolAddress((void**)&W2tL, g_W2tL);

    cudaFuncSetAttribute(bgemm_kernel, cudaFuncAttributeMaxDynamicSharedMemorySize, TC_SMEM);
    cudaFuncSetAttribute(flash2_kernel, cudaFuncAttributeMaxDynamicSharedMemorySize, FSMEM);

    dim3 blk(256);
    const int n8 = MROWS * HID / 8;

    split_kernel<<<n8/256, blk>>>(src,    srcH, srcL, n8);
    split_kernel<<<n8/256, blk>>>(hidden, hidH, hidL, n8);
    tsplit_kernel<<<dim3(HID/32, HID/32), blk>>>(W1, W1tH, W1tL, HID, HID);
    tsplit_kernel<<<dim3(HID/32, HID/32), blk>>>(W2, W2tH, W2tL, HID, HID);
    tsplit_kernel<<<dim3((NKV*HD)/32, HID/32), blk>>>(Wk, WktH, WktL, HID, NKV*HD);
    tsplit_kernel<<<dim3((NKV*HD)/32, HID/32), blk>>>(Wv, WvtH, WvtL, HID, NKV*HD);
    tsplit_kernel<<<dim3(HID/32, HID/32), blk>>>(Wq, WqtH, WqtL, HID, HID);
    tsplit_kernel<<<dim3(HID/32, HID/32), blk>>>(Wd, WdtH, WdtL, HID, HID);

    // 1. Pl1 = relu(src @ W1 + b1)
    bgemm_kernel<<<dim3(HID/128, MROWS/128), blk, TC_SMEM>>>(
        srcH, srcL, W1tH, W1tL, b1, nullptr, pPl1, Pl1H, Pl1L,
        HID, M_RELU | M_WRITEC | M_SPLIT, 0);
    // 2. P = (Pl1 @ W2 + b2) + Pl1
    bgemm_kernel<<<dim3(HID/128, MROWS/128), blk, TC_SMEM>>>(
        Pl1H, Pl1L, W2tH, W2tL, b2, pPl1, nullptr, PH, PL,
        HID, M_RES | M_SPLIT, 0);
    // 3. K -> [B*NKV][S][HD]
    bgemm_kernel<<<dim3((NKV*HD)/128, MROWS/128), blk, TC_SMEM>>>(
        PH, PL, WktH, WktL, bk, nullptr, nullptr, KHp, KLp,
        NKV*HD, M_SCAT, NKV);
    // 4. V -> [B*NKV][HD][S] (transposed)
    bgemm_kernel<<<dim3((NKV*HD)/128, MROWS/128), blk, TC_SMEM>>>(
        PH, PL, WvtH, WvtL, bv, nullptr, nullptr, VtHp, VtLp,
        NKV*HD, M_TSCAT, NKV);
    // 5. Q -> [B*NH][S][HD]
    bgemm_kernel<<<dim3(HID/128, MROWS/128), blk, TC_SMEM>>>(
        hidH, hidL, WqtH, WqtL, bq, nullptr, nullptr, QH, QL,
        HID, M_SCAT, NH);
    // 6. flash attention
    flash2_kernel<<<dim3(SEQ/128, BATCH*NH), blk, FSMEM>>>(
        QH, QL, KHp, KLp, VtHp, VtLp, ctxH, ctxL);
    // 7. pre = ctx @ Wd + bd
    bgemm_kernel<<<dim3(HID/128, MROWS/128), blk, TC_SMEM>>>(
        ctxH, ctxL, WdtH, WdtL, bd, nullptr, pPre, nullptr, nullptr,
        HID, M_WRITEC, 0);
    // 8. out = layernorm(pre + hidden)
    ln_kernel<<<MROWS, 256>>>(pPre, hidden, gamma, beta, out);
}

// round 8
// speedup vs baseline: 3.7108x; 1.0140x over previous
#include <cuda_runtime.h>
#include <cuda_bf16.h>
#include <math.h>
#include <stdint.h>

// Problem constants (fixed shapes)
#define BATCH 2
#define SEQ   2048
#define HID   2048
#define NH    16
#define NKV   4
#define GRP   4
#define HD    128
#define MROWS (BATCH*SEQ)     // 4096
#define KDIM  2048

typedef __nv_bfloat16 bf16;

// ---------------- scratch (device globals) ----------------------------------
__device__ float g_Pl1[MROWS*HID];
__device__ float g_pre[MROWS*HID];

// GEMM operands: TILED-SWIZZLED layout (see tiled_off)
__device__ __align__(16) bf16 g_srcH[MROWS*HID], g_srcL[MROWS*HID];
__device__ __align__(16) bf16 g_hidH[MROWS*HID], g_hidL[MROWS*HID];
__device__ __align__(16) bf16 g_Pl1H[MROWS*HID], g_Pl1L[MROWS*HID];
__device__ __align__(16) bf16 g_PH  [MROWS*HID], g_PL  [MROWS*HID];
__device__ __align__(16) bf16 g_ctxH[MROWS*HID], g_ctxL[MROWS*HID];

__device__ __align__(16) bf16 g_WqtH[HID*HID],      g_WqtL[HID*HID];
__device__ __align__(16) bf16 g_WktH[(NKV*HD)*HID], g_WktL[(NKV*HD)*HID];
__device__ __align__(16) bf16 g_WvtH[(NKV*HD)*HID], g_WvtL[(NKV*HD)*HID];
__device__ __align__(16) bf16 g_WdtH[HID*HID],      g_WdtL[HID*HID];
__device__ __align__(16) bf16 g_W1tH[HID*HID],      g_W1tL[HID*HID];
__device__ __align__(16) bf16 g_W2tH[HID*HID],      g_W2tL[HID*HID];

// flash operands: FLAT layout
__device__ __align__(16) bf16 g_QH [MROWS*HID],      g_QL [MROWS*HID];     // [B*NH][S][HD]
__device__ __align__(16) bf16 g_KH [MROWS*NKV*HD],   g_KL [MROWS*NKV*HD];  // [B*NKV][S][HD]
__device__ __align__(16) bf16 g_VtH[MROWS*NKV*HD],   g_VtL[MROWS*NKV*HD];  // [B*NKV][HD][S]

// ================= helpers ==================================================
__device__ __forceinline__ void mma_bf16(float (&d)[4],
                                         const uint32_t* a, const uint32_t* b) {
    asm volatile(
        "mma.sync.aligned.m16n8k16.row.col.f32.bf16.bf16.f32 "
        "{%0,%1,%2,%3}, {%4,%5,%6,%7}, {%8,%9}, {%0,%1,%2,%3};\n"
        : "+f"(d[0]), "+f"(d[1]), "+f"(d[2]), "+f"(d[3])
        : "r"(a[0]), "r"(a[1]), "r"(a[2]), "r"(a[3]), "r"(b[0]), "r"(b[1]));
}

__device__ __forceinline__ void ldsm4(uint32_t* r, uint32_t addr) {
    asm volatile("ldmatrix.sync.aligned.m8n8.x4.shared.b16 {%0,%1,%2,%3}, [%4];"
        : "=r"(r[0]), "=r"(r[1]), "=r"(r[2]), "=r"(r[3]) : "r"(addr));
}

__device__ __forceinline__ float ex2(float x) {
    float y; asm("ex2.approx.ftz.f32 %0, %1;" : "=f"(y) : "f"(x)); return y;
}

__device__ __forceinline__ void split2(float v0, float v1,
                                       uint32_t& hi, uint32_t& lo) {
    __nv_bfloat162 h = __floats2bfloat162_rn(v0, v1);
    hi = *reinterpret_cast<uint32_t*>(&h);
    __nv_bfloat162 l = __floats2bfloat162_rn(v0 - __bfloat162float(h.x),
                                             v1 - __bfloat162float(h.y));
    lo = *reinterpret_cast<uint32_t*>(&l);
}

__device__ __forceinline__ uint32_t smem_u32(const void* p) {
    uint32_t a;
    asm("{ .reg .u64 t; cvta.to.shared.u64 t, %1; cvt.u32.u64 %0, t; }"
        : "=r"(a) : "l"(p));
    return a;
}

// bulk async copy global->shared with mbarrier tx accounting
__device__ __forceinline__ void bulkcp(uint32_t dst, const void* src,
                                       uint32_t bytes, uint32_t mbar) {
    asm volatile(
        "cp.async.bulk.shared::cluster.global.mbarrier::complete_tx::bytes "
        "[%0], [%1], %2, [%3];"
        :: "r"(dst), "l"(src), "r"(bytes), "r"(mbar) : "memory");
}

#define MBAR_INIT(mbar, cnt) \
    asm volatile("mbarrier.init.shared.b64 [%0], %1;" \
                 :: "r"((uint32_t)(mbar)), "r"((uint32_t)(cnt)) : "memory")
#define MBAR_EXPECT(mbar, bytes) \
    asm volatile("mbarrier.arrive.expect_tx.shared.b64 _, [%0], %1;" \
                 :: "r"((uint32_t)(mbar)), "r"((uint32_t)(bytes)) : "memory")

#define MBAR_WAIT(mbar, par) do {                                              \
    uint32_t _m = (uint32_t)(mbar), _p = (uint32_t)(par), _d;                  \
    asm volatile("{\n\t.reg .pred p;\n\t"                                      \
        "mbarrier.try_wait.parity.acquire.cta.shared::cta.b64 p, [%1], %2;\n\t"\
        "selp.b32 %0, 1, 0, p;\n\t}" : "=r"(_d) : "r"(_m), "r"(_p) : "memory");\
    if (!_d) {                                                                 \
        asm volatile("{\n\t.reg .pred P1;\n\t"                                 \
            "WL_%=:\n\t"                                                       \
            "mbarrier.try_wait.parity.acquire.cta.shared::cta.b64 P1, [%0], %1, 0x989680;\n\t" \
            "@P1 bra.uni WD_%=;\n\t"                                           \
            "bra.uni WL_%=;\n\t"                                               \
            "WD_%=:\n\t}" :: "r"(_m), "r"(_p) : "memory");                     \
    } } while (0)

// ---- tiled-swizzled GEMM operand layout -------------------------------------
// 128-row x 64-col (bf16) blocks, 16384 B each, blocks row-major in (mb, kb).
// Within a block: row ri (0..127) at ri*128; 16B chunk ci stored at (ci^(ri&7)).
__device__ __forceinline__ size_t tiled_off(int r, int kchunk, int Kd) {
    int mb = r >> 7, kb = kchunk >> 3;
    int ri = r & 127, ci = kchunk & 7;
    int cs = ci ^ (ri & 7);
    return ((size_t)(mb * (Kd >> 6) + kb)) * 16384 + ri * 128 + cs * 16;
}

// ================= split kernels (write tiled layout) ========================
__global__ __launch_bounds__(256)
void split_kernel(const float* __restrict__ x, bf16* __restrict__ hi,
                  bf16* __restrict__ lo, int n8)
{
    int i = blockIdx.x * blockDim.x + threadIdx.x;
    if (i >= n8) return;
    int r  = i >> 8;
    int kc = i & 255;
    const float4* xp = (const float4*)x + (size_t)i * 2;
    float4 v0 = xp[0], v1 = xp[1];
    uint32_t h0,l0,h1,l1,h2,l2,h3,l3;
    split2(v0.x, v0.y, h0, l0); split2(v0.z, v0.w, h1, l1);
    split2(v1.x, v1.y, h2, l2); split2(v1.z, v1.w, h3, l3);
    size_t o = tiled_off(r, kc, 2048);
    *(uint4*)((char*)hi + o) = make_uint4(h0, h1, h2, h3);
    *(uint4*)((char*)lo + o) = make_uint4(l0, l1, l2, l3);
}

// W [K][N] fp32 -> TH/TL tiled [N][K] bf16 (transpose + split + tile-swizzle)
__global__ __launch_bounds__(256)
void tsplit_kernel(const float* __restrict__ W, bf16* __restrict__ TH,
                   bf16* __restrict__ TL, int Kd, int Nd)
{
    __shared__ float tl[32][33];
    int n0 = blockIdx.x * 32, k0 = blockIdx.y * 32;
    int tx = threadIdx.x & 31;
    int ty = threadIdx.x >> 5;
    #pragma unroll
    for (int i = 0; i < 4; i++)
        tl[ty + 8*i][tx] = W[(size_t)(k0 + ty + 8*i) * Nd + n0 + tx];
    __syncthreads();
    #pragma unroll
    for (int i = 0; i < 4; i++) {
        float v = tl[tx][ty + 8*i];
        bf16 h = __float2bfloat16(v);
        int n_ = n0 + ty + 8*i, k_ = k0 + tx;
        size_t o = tiled_off(n_, k_ >> 3, 2048) + (size_t)(k_ & 7) * 2;
        *(bf16*)((char*)TH + o) = h;
        *(bf16*)((char*)TL + o) = __float2bfloat16(v - __bfloat162float(h));
    }
}

// ================= bulk-load split-bf16 tensor GEMM =========================
// Tile 128x128, ktile 64, 16 warps (m32 x n32 each), 2-stage bulk pipeline.
#define TPL   16384
#define TSTG  (4*TPL)                 // 65536
#define TC_SMEM (64 + 2*TSTG)         // 131136

#define M_RELU   1
#define M_RES    2
#define M_WRITEC 8
#define M_SPLIT  16
#define M_SCAT   32
#define M_TSCAT  64

__global__ __launch_bounds__(512)
void bgemm_kernel(const bf16* __restrict__ AH, const bf16* __restrict__ AL,
                  const bf16* __restrict__ BtH, const bf16* __restrict__ BtL,
                  const float* __restrict__ bias, const float* __restrict__ res,
                  float* __restrict__ C, bf16* __restrict__ CH, bf16* __restrict__ CL,
                  int N, int mode, int heads)
{
    extern __shared__ char smraw[];
    const uint32_t sb  = smem_u32(smraw);
    const uint32_t mb0 = sb;
    const uint32_t sb0 = sb + 64;

    const int tid  = threadIdx.x;
    const int wid  = tid >> 5;
    const int lane = tid & 31;
    const int l15  = lane & 15;
    const int lsel = lane >> 4;
    const int warpM = (wid & 3) * 32;
    const int warpN = (wid >> 2) * 32;
    const int mBase = blockIdx.y * 128;
    const int nBase = blockIdx.x * 128;

    if (tid == 0) { MBAR_INIT(mb0, 1); MBAR_INIT(mb0 + 8, 1); }
    __syncthreads();

    float acc[2][4][4];
    #pragma unroll
    for (int i = 0; i < 2; i++)
        #pragma unroll
        for (int j = 0; j < 4; j++)
            #pragma unroll
            for (int c = 0; c < 4; c++) acc[i][j][c] = 0.f;

#define TLOAD(kt, bf_) do { if (tid == 0) {                                    \
        MBAR_EXPECT(mb0 + (bf_)*8, (uint32_t)TSTG);                            \
        uint32_t st_ = sb0 + (bf_)*TSTG;                                       \
        size_t ao_ = ((size_t)(blockIdx.y * 32 + (kt))) * TPL;                 \
        size_t bo_ = ((size_t)(blockIdx.x * 32 + (kt))) * TPL;                 \
        bulkcp(st_,           (const char*)AH  + ao_, TPL, mb0 + (bf_)*8);     \
        bulkcp(st_ +   TPL,   (const char*)AL  + ao_, TPL, mb0 + (bf_)*8);     \
        bulkcp(st_ + 2*TPL,   (const char*)BtH + bo_, TPL, mb0 + (bf_)*8);     \
        bulkcp(st_ + 3*TPL,   (const char*)BtL + bo_, TPL, mb0 + (bf_)*8);     \
    } } while (0)

    const int nk = KDIM / 64;        // 32 stages
    TLOAD(0, 0);

    for (int kt = 0; kt < nk; kt++) {
        const int buf = kt & 1;
        if (kt + 1 < nk) TLOAD(kt + 1, buf ^ 1);
        MBAR_WAIT(mb0 + buf * 8, (kt >> 1) & 1);
        const uint32_t st = sb0 + buf * TSTG;

        #pragma unroll
        for (int ks = 0; ks < 4; ks++) {
            uint32_t ah[2][4], al[2][4], bh[4][2], bl[4][2];
            #pragma unroll
            for (int mi = 0; mi < 2; mi++) {
                int ar = warpM + mi * 16 + l15;
                uint32_t ad = st + ar * 128 + (((ks * 2 + lsel) ^ (ar & 7)) << 4);
                ldsm4(ah[mi], ad);
                ldsm4(al[mi], ad + TPL);
            }
            #pragma unroll
            for (int n2 = 0; n2 < 2; n2++) {
                int br = warpN + n2 * 16 + l15;
                uint32_t bd = st + 2*TPL + br * 128
                            + (((ks * 2 + lsel) ^ (br & 7)) << 4);
                uint32_t r[4];
                ldsm4(r, bd);
                bh[2*n2][0]   = r[0]; bh[2*n2][1]   = r[2];
                bh[2*n2+1][0] = r[1]; bh[2*n2+1][1] = r[3];
                ldsm4(r, bd + TPL);
                bl[2*n2][0]   = r[0]; bl[2*n2][1]   = r[2];
                bl[2*n2+1][0] = r[1]; bl[2*n2+1][1] = r[3];
            }
            #pragma unroll
            for (int mi = 0; mi < 2; mi++)
                #pragma unroll
                for (int ni = 0; ni < 4; ni++) {
                    mma_bf16(acc[mi][ni], al[mi], bh[ni]);
                    mma_bf16(acc[mi][ni], ah[mi], bl[ni]);
                    mma_bf16(acc[mi][ni], ah[mi], bh[ni]);
                }
        }
        __syncthreads();   // all reads of buf done before it is refilled
    }
#undef TLOAD

    // -------- epilogue --------
    const int g  = lane >> 2;
    const int t4 = lane & 3;
    const int rw = mBase + warpM + g;
    const int cw = nBase + warpN + 2 * t4;
    #pragma unroll
    for (int mi = 0; mi < 2; mi++) {
        #pragma unroll
        for (int h = 0; h < 2; h++) {
            const int r = rw + mi * 16 + h * 8;
            const int b = r / SEQ, s = r - (r / SEQ) * SEQ;
            #pragma unroll
            for (int ni = 0; ni < 4; ni++) {
                const int c0 = cw + ni * 8;
                float v0 = acc[mi][ni][h*2 + 0] + bias[c0];
                float v1 = acc[mi][ni][h*2 + 1] + bias[c0 + 1];
                if (mode & M_RELU) { v0 = fmaxf(v0, 0.f); v1 = fmaxf(v1, 0.f); }
                if (mode & M_RES) {
                    v0 += res[(size_t)r * N + c0];
                    v1 += res[(size_t)r * N + c0 + 1];
                }
                if (mode & M_WRITEC) {
                    C[(size_t)r * N + c0]     = v0;
                    C[(size_t)r * N + c0 + 1] = v1;
                }
                if (mode & (M_SPLIT | M_SCAT | M_TSCAT)) {
                    uint32_t hi, lo;
                    split2(v0, v1, hi, lo);
                    if (mode & M_SPLIT) {
                        size_t o = tiled_off(r, c0 >> 3, 2048)
                                 + (size_t)(c0 & 7) * 2;
                        *(uint32_t*)((char*)CH + o) = hi;
                        *(uint32_t*)((char*)CL + o) = lo;
                    } else if (mode & M_SCAT) {
                        int head = c0 >> 7, d = c0 & 127;
                        size_t o = (((size_t)(b * heads + head)) * SEQ + s) * HD + d;
                        *(uint32_t*)(CH + o) = hi;
                        *(uint32_t*)(CL + o) = lo;
                    } else {
                        int head = c0 >> 7, d = c0 & 127;
                        size_t o = (((size_t)(b * NKV + head)) * HD + d) * SEQ + s;
                        __nv_bfloat162 H = *reinterpret_cast<__nv_bfloat162*>(&hi);
                        __nv_bfloat162 L = *reinterpret_cast<__nv_bfloat162*>(&lo);
                        CH[o] = H.x;  CH[o + SEQ] = H.y;
                        CL[o] = L.x;  CL[o + SEQ] = L.y;
                    }
                }
            }
        }
    }
}

// ================= tensor-core flash attention (bulk loads) =================
#define FQP 272
#define FVP 144
#define FQ_BYTES (128*FQP)
#define FK_BYTES (64*FQP)
#define FV_BYTES (128*FVP)
#define FK_STAGE (2*FK_BYTES)
#define FV_STAGE (2*FV_BYTES)
#define OFF_Q 0
#define OFF_K (2*FQ_BYTES)
#define OFF_V (OFF_K + 2*FK_STAGE)
#define OFF_MB (OFF_V + 2*FV_STAGE)
#define FSMEM (OFF_MB + 64)

__global__ __launch_bounds__(256, 1)
void flash2_kernel(const bf16* __restrict__ QH, const bf16* __restrict__ QL,
                   const bf16* __restrict__ KH, const bf16* __restrict__ KL,
                   const bf16* __restrict__ VtH, const bf16* __restrict__ VtL,
                   bf16* __restrict__ ctxH, bf16* __restrict__ ctxL)
{
    extern __shared__ char smraw[];
    const uint32_t sb  = smem_u32(smraw);
    const uint32_t fmb = sb + OFF_MB;

    const int tid  = threadIdx.x;
    const int wid  = tid >> 5;
    const int lane = tid & 31;
    const int g    = lane >> 2;
    const int t4   = lane & 3;
    const int l15  = lane & 15;
    const int l16  = (lane >> 4) * 16;

    const int qb = blockIdx.x;
    const int bh = blockIdx.y;
    const int b  = bh / NH;
    const int h  = bh % NH;
    const int kv = b * NKV + (h / GRP);

    const bf16* Qh  = QH  + ((size_t)bh * SEQ + qb * 128) * HD;
    const bf16* Ql  = QL  + ((size_t)bh * SEQ + qb * 128) * HD;
    const bf16* Kh  = KH  + (size_t)kv * SEQ * HD;
    const bf16* Kl  = KL  + (size_t)kv * SEQ * HD;
    const bf16* Vth = VtH + (size_t)kv * HD * SEQ;
    const bf16* Vtl = VtL + (size_t)kv * HD * SEQ;

    if (tid == 0) { MBAR_INIT(fmb, 1); MBAR_INIT(fmb + 8, 1); }
    __syncthreads();

#define KVB(kc, st) do {                                                       \
        for (int o = tid; o < 384; o += 256) {                                 \
            if (o < 128) {                                                     \
                int pl = o >> 6, rr = o & 63;                                  \
                bulkcp(sb + OFF_K + (st)*FK_STAGE + pl*FK_BYTES + rr*FQP,      \
                       (pl ? Kl : Kh) + (size_t)((kc) + rr) * HD, 256,         \
                       fmb + (st)*8);                                          \
            } else {                                                           \
                int q_ = o - 128; int pl = q_ >> 7, rv = q_ & 127;             \
                bulkcp(sb + OFF_V + (st)*FV_STAGE + pl*FV_BYTES + rv*FVP,      \
                       (pl ? Vtl : Vth) + (size_t)rv * SEQ + (kc), 128,        \
                       fmb + (st)*8);                                          \
            } } } while (0)

#define LOADKV(kc, st) do {                                                    \
        if (tid == 0) MBAR_EXPECT(fmb + (st)*8, 65536);                        \
        KVB(kc, st); } while (0)

    if (tid == 0) MBAR_EXPECT(fmb, 131072);
    {
        int pl = tid >> 7, rq = tid & 127;
        bulkcp(sb + OFF_Q + pl * FQ_BYTES + rq * FQP,
               (pl ? Ql : Qh) + (size_t)rq * HD, 256, fmb);
    }
    KVB(0, 0);

    const int m0r = wid * 16;
    float O[16][4];
    #pragma unroll
    for (int j = 0; j < 16; j++)
        #pragma unroll
        for (int c = 0; c < 4; c++) O[j][c] = 0.f;
    float mrow0 = -1e30f, mrow1 = -1e30f, lrow0 = 0.f, lrow1 = 0.f;
    const float c1 = 0.08838834764831845f * 1.4426950408889634f;

    for (int ic = 0; ic < SEQ / 64; ic++) {
        const int buf = ic & 1;
        if (ic + 1 < SEQ / 64) LOADKV((ic + 1) * 64, buf ^ 1);
        MBAR_WAIT(fmb + buf * 8, (ic >> 1) & 1);

        float s_[8][4];
        #pragma unroll
        for (int j = 0; j < 8; j++)
            #pragma unroll
            for (int c = 0; c < 4; c++) s_[j][c] = 0.f;

        const uint32_t kbase = sb + OFF_K + buf * FK_STAGE;
        #pragma unroll
        for (int kk = 0; kk < 8; kk++) {
            uint32_t aH[4], aL[4];
            uint32_t aoq = (uint32_t)((m0r + l15) * FQP + kk * 32 + l16);
            ldsm4(aH, sb + OFF_Q + aoq);
            ldsm4(aL, sb + OFF_Q + FQ_BYTES + aoq);
            #pragma unroll
            for (int j2 = 0; j2 < 4; j2++) {
                uint32_t bo = (uint32_t)((j2 * 16 + l15) * FQP + kk * 32 + l16);
                uint32_t rH[4], rL[4];
                ldsm4(rH, kbase + bo);
                ldsm4(rL, kbase + FK_BYTES + bo);
                uint32_t bh0[2] = { rH[0], rH[2] }, bh1[2] = { rH[1], rH[3] };
                uint32_t bl0[2] = { rL[0], rL[2] }, bl1[2] = { rL[1], rL[3] };
                mma_bf16(s_[2*j2],   aL, bh0);
                mma_bf16(s_[2*j2],   aH, bl0);
                mma_bf16(s_[2*j2],   aH, bh0);
                mma_bf16(s_[2*j2+1], aL, bh1);
                mma_bf16(s_[2*j2+1], aH, bl1);
                mma_bf16(s_[2*j2+1], aH, bh1);
            }
        }

        float zx0 = -1e30f, zx1 = -1e30f;
        #pragma unroll
        for (int j = 0; j < 8; j++) {
            zx0 = fmaxf(zx0, fmaxf(s_[j][0], s_[j][1]));
            zx1 = fmaxf(zx1, fmaxf(s_[j][2], s_[j][3]));
        }
        zx0 *= c1; zx1 *= c1;
        #pragma unroll
        for (int w = 1; w <= 2; w <<= 1) {
            zx0 = fmaxf(zx0, __shfl_xor_sync(0xffffffffu, zx0, w));
            zx1 = fmaxf(zx1, __shfl_xor_sync(0xffffffffu, zx1, w));
        }
        float mn0 = fmaxf(mrow0, zx0), mn1 = fmaxf(mrow1, zx1);
        float al0 = ex2(mrow0 - mn0),  al1 = ex2(mrow1 - mn1);
        float rs0 = 0.f, rs1 = 0.f;
        #pragma unroll
        for (int j = 0; j < 8; j++) {
            s_[j][0] = ex2(fmaf(s_[j][0], c1, -mn0));
            s_[j][1] = ex2(fmaf(s_[j][1], c1, -mn0));
            s_[j][2] = ex2(fmaf(s_[j][2], c1, -mn1));
            s_[j][3] = ex2(fmaf(s_[j][3], c1, -mn1));
            rs0 += s_[j][0] + s_[j][1];
            rs1 += s_[j][2] + s_[j][3];
        }
        #pragma unroll
        for (int w = 1; w <= 2; w <<= 1) {
            rs0 += __shfl_xor_sync(0xffffffffu, rs0, w);
            rs1 += __shfl_xor_sync(0xffffffffu, rs1, w);
        }
        lrow0 = lrow0 * al0 + rs0;
        lrow1 = lrow1 * al1 + rs1;
        mrow0 = mn0; mrow1 = mn1;

        #pragma unroll
        for (int j = 0; j < 16; j++) {
            O[j][0] *= al0; O[j][1] *= al0;
            O[j][2] *= al1; O[j][3] *= al1;
        }

        uint32_t ph[4][4], pl[4][4];
        #pragma unroll
        for (int kk = 0; kk < 4; kk++) {
            split2(s_[2*kk][0],   s_[2*kk][1],   ph[kk][0], pl[kk][0]);
            split2(s_[2*kk][2],   s_[2*kk][3],   ph[kk][1], pl[kk][1]);
            split2(s_[2*kk+1][0], s_[2*kk+1][1], ph[kk][2], pl[kk][2]);
            split2(s_[2*kk+1][2], s_[2*kk+1][3], ph[kk][3], pl[kk][3]);
        }

        const uint32_t vbase = sb + OFF_V + buf * FV_STAGE;
        #pragma unroll
        for (int kk = 0; kk < 4; kk++) {
            #pragma unroll
            for (int j2 = 0; j2 < 8; j2++) {
                uint32_t vo = (uint32_t)((j2 * 16 + l15) * FVP + kk * 32 + l16);
                uint32_t rH[4], rL[4];
                ldsm4(rH, vbase + vo);
                ldsm4(rL, vbase + FV_BYTES + vo);
                uint32_t bh0[2] = { rH[0], rH[2] }, bh1[2] = { rH[1], rH[3] };
                uint32_t bl0[2] = { rL[0], rL[2] }, bl1[2] = { rL[1], rL[3] };
                mma_bf16(O[2*j2],   pl[kk], bh0);
                mma_bf16(O[2*j2],   ph[kk], bl0);
                mma_bf16(O[2*j2],   ph[kk], bh0);
                mma_bf16(O[2*j2+1], pl[kk], bh1);
                mma_bf16(O[2*j2+1], ph[kk], bl1);
                mma_bf16(O[2*j2+1], ph[kk], bh1);
            }
        }
        __syncthreads();
    }
#undef LOADKV
#undef KVB

    const float inv0 = 1.f / lrow0, inv1 = 1.f / lrow1;
    const int q0 = qb * 128 + m0r + g;
    const int q1 = q0 + 8;
    const int row0 = b * SEQ + q0;
    const int row1 = b * SEQ + q1;
    #pragma unroll
    for (int j = 0; j < 16; j++) {
        const int colg = h * HD + j * 8 + 2 * t4;
        uint32_t hi, lo;
        split2(O[j][0] * inv0, O[j][1] * inv0, hi, lo);
        size_t o0 = tiled_off(row0, colg >> 3, 2048) + (size_t)(colg & 7) * 2;
        *(uint32_t*)((char*)ctxH + o0) = hi;
        *(uint32_t*)((char*)ctxL + o0) = lo;
        split2(O[j][2] * inv1, O[j][3] * inv1, hi, lo);
        size_t o1 = tiled_off(row1, colg >> 3, 2048) + (size_t)(colg & 7) * 2;
        *(uint32_t*)((char*)ctxH + o1) = hi;
        *(uint32_t*)((char*)ctxL + o1) = lo;
    }
}

// ---------------- residual + layernorm -------------------------------------
__device__ __forceinline__ float block_sum256(float v, float* sred)
{
    #pragma unroll
    for (int off = 16; off; off >>= 1) v += __shfl_xor_sync(0xffffffffu, v, off);
    int warp = threadIdx.x >> 5;
    if ((threadIdx.x & 31) == 0) sred[warp] = v;
    __syncthreads();
    if (threadIdx.x < 32) {
        float x = (threadIdx.x < 8) ? sred[threadIdx.x] : 0.f;
        #pragma unroll
        for (int off = 4; off; off >>= 1) x += __shfl_xor_sync(0xffffffffu, x, off);
        if (threadIdx.x == 0) sred[0] = x;
    }
    __syncthreads();
    float r = sred[0];
    __syncthreads();
    return r;
}

__global__ __launch_bounds__(256)
void ln_kernel(const float* __restrict__ x, const float* __restrict__ resid,
               const float* __restrict__ gamma, const float* __restrict__ beta,
               float* __restrict__ out)
{
    __shared__ float sred[32];
    const size_t row = blockIdx.x;
    const int tid = threadIdx.x;
    const float* xr = x     + row * HID;
    const float* rr = resid + row * HID;

    float v[8];
    float s = 0.f;
    #pragma unroll
    for (int t = 0; t < 8; t++) {
        int c = tid + t * 256;
        v[t] = xr[c] + rr[c];
        s += v[t];
    }
    float mean = block_sum256(s, sred) * (1.f / HID);

    float s2 = 0.f;
    #pragma unroll
    for (int t = 0; t < 8; t++) { float d = v[t] - mean; s2 += d * d; }
    float var = block_sum256(s2, sred) * (1.f / HID);
    float rstd = rsqrtf(var + 1e-12f);

    float* orow = out + row * HID;
    #pragma unroll
    for (int t = 0; t < 8; t++) {
        int c = tid + t * 256;
        orow[c] = (v[t] - mean) * rstd * gamma[c] + beta[c];
    }
}

// ---------------- launch ----------------------------------------------------
extern "C" void kernel_launch(void* const* d_in, const int* in_sizes, int n_in,
                              void* d_out, int out_size)
{
    const float* hidden = (const float*)d_in[0];
    const float* src    = (const float*)d_in[1];
    const float* Wq = (const float*)d_in[2];
    const float* bq = (const float*)d_in[3];
    const float* Wk = (const float*)d_in[4];
    const float* bk = (const float*)d_in[5];
    const float* Wv = (const float*)d_in[6];
    const float* bv = (const float*)d_in[7];
    const float* Wd = (const float*)d_in[8];
    const float* bd = (const float*)d_in[9];
    const float* W1 = (const float*)d_in[10];
    const float* b1 = (const float*)d_in[11];
    const float* W2 = (const float*)d_in[12];
    const float* b2 = (const float*)d_in[13];
    const float* gamma = (const float*)d_in[14];
    const float* beta  = (const float*)d_in[15];
    float* out = (float*)d_out;

    float *pPl1, *pPre;
    cudaGetSymbolAddress((void**)&pPl1, g_Pl1);
    cudaGetSymbolAddress((void**)&pPre, g_pre);

    bf16 *srcH,*srcL,*hidH,*hidL,*Pl1H,*Pl1L,*PH,*PL,*ctxH,*ctxL;
    bf16 *QH,*QL,*KHp,*KLp,*VtHp,*VtLp;
    cudaGetSymbolAddress((void**)&srcH, g_srcH); cudaGetSymbolAddress((void**)&srcL, g_srcL);
    cudaGetSymbolAddress((void**)&hidH, g_hidH); cudaGetSymbolAddress((void**)&hidL, g_hidL);
    cudaGetSymbolAddress((void**)&Pl1H, g_Pl1H); cudaGetSymbolAddress((void**)&Pl1L, g_Pl1L);
    cudaGetSymbolAddress((void**)&PH,   g_PH);   cudaGetSymbolAddress((void**)&PL,   g_PL);
    cudaGetSymbolAddress((void**)&ctxH, g_ctxH); cudaGetSymbolAddress((void**)&ctxL, g_ctxL);
    cudaGetSymbolAddress((void**)&QH,   g_QH);   cudaGetSymbolAddress((void**)&QL,   g_QL);
    cudaGetSymbolAddress((void**)&KHp,  g_KH);   cudaGetSymbolAddress((void**)&KLp,  g_KL);
    cudaGetSymbolAddress((void**)&VtHp, g_VtH);  cudaGetSymbolAddress((void**)&VtLp, g_VtL);

    bf16 *WqtH,*WqtL,*WktH,*WktL,*WvtH,*WvtL,*WdtH,*WdtL,*W1tH,*W1tL,*W2tH,*W2tL;
    cudaGetSymbolAddress((void**)&WqtH, g_WqtH); cudaGetSymbolAddress((void**)&WqtL, g_WqtL);
    cudaGetSymbolAddress((void**)&WktH, g_WktH); cudaGetSymbolAddress((void**)&WktL, g_WktL);
    cudaGetSymbolAddress((void**)&WvtH, g_WvtH); cudaGetSymbolAddress((void**)&WvtL, g_WvtL);
    cudaGetSymbolAddress((void**)&WdtH, g_WdtH); cudaGetSymbolAddress((void**)&WdtL, g_WdtL);
    cudaGetSymbolAddress((void**)&W1tH, g_W1tH); cudaGetSymbolAddress((void**)&W1tL, g_W1tL);
    cudaGetSymbolAddress((void**)&W2tH, g_W2tH); cudaGetSymbolAddress((void**)&W2tL, g_W2tL);

    cudaFuncSetAttribute(bgemm_kernel, cudaFuncAttributeMaxDynamicSharedMemorySize, TC_SMEM);
    cudaFuncSetAttribute(flash2_kernel, cudaFuncAttributeMaxDynamicSharedMemorySize, FSMEM);

    dim3 blk(256);
    dim3 blkG(512);
    const int n8 = MROWS * HID / 8;

    split_kernel<<<n8/256, blk>>>(src,    srcH, srcL, n8);
    split_kernel<<<n8/256, blk>>>(hidden, hidH, hidL, n8);
    tsplit_kernel<<<dim3(HID/32, HID/32), blk>>>(W1, W1tH, W1tL, HID, HID);
    tsplit_kernel<<<dim3(HID/32, HID/32), blk>>>(W2, W2tH, W2tL, HID, HID);
    tsplit_kernel<<<dim3((NKV*HD)/32, HID/32), blk>>>(Wk, WktH, WktL, HID, NKV*HD);
    tsplit_kernel<<<dim3((NKV*HD)/32, HID/32), blk>>>(Wv, WvtH, WvtL, HID, NKV*HD);
    tsplit_kernel<<<dim3(HID/32, HID/32), blk>>>(Wq, WqtH, WqtL, HID, HID);
    tsplit_kernel<<<dim3(HID/32, HID/32), blk>>>(Wd, WdtH, WdtL, HID, HID);

    // 1. Pl1 = relu(src @ W1 + b1)
    bgemm_kernel<<<dim3(HID/128, MROWS/128), blkG, TC_SMEM>>>(
        srcH, srcL, W1tH, W1tL, b1, nullptr, pPl1, Pl1H, Pl1L,
        HID, M_RELU | M_WRITEC | M_SPLIT, 0);
    // 2. P = (Pl1 @ W2 + b2) + Pl1
    bgemm_kernel<<<dim3(HID/128, MROWS/128), blkG, TC_SMEM>>>(
        Pl1H, Pl1L, W2tH, W2tL, b2, pPl1, nullptr, PH, PL,
        HID, M_RES | M_SPLIT, 0);
    // 3. K -> [B*NKV][S][HD]
    bgemm_kernel<<<dim3((NKV*HD)/128, MROWS/128), blkG, TC_SMEM>>>(
        PH, PL, WktH, WktL, bk, nullptr, nullptr, KHp, KLp,
        NKV*HD, M_SCAT, NKV);
    // 4. V -> [B*NKV][HD][S] (transposed)
    bgemm_kernel<<<dim3((NKV*HD)/128, MROWS/128), blkG, TC_SMEM>>>(
        PH, PL, WvtH, WvtL, bv, nullptr, nullptr, VtHp, VtLp,
        NKV*HD, M_TSCAT, NKV);
    // 5. Q -> [B*NH][S][HD]
    bgemm_kernel<<<dim3(HID/128, MROWS/128), blkG, TC_SMEM>>>(
        hidH, hidL, WqtH, WqtL, bq, nullptr, nullptr, QH, QL,
        HID, M_SCAT, NH);
    // 6. flash attention
    flash2_kernel<<<dim3(SEQ/128, BATCH*NH), blk, FSMEM>>>(
        QH, QL, KHp, KLp, VtHp, VtLp, ctxH, ctxL);
    // 7. pre = ctx @ Wd + bd
    bgemm_kernel<<<dim3(HID/128, MROWS/128), blkG, TC_SMEM>>>(
        ctxH, ctxL, WdtH, WdtL, bd, nullptr, pPre, nullptr, nullptr,
        HID, M_WRITEC, 0);
    // 8. out = layernorm(pre + hidden)
    ln_kernel<<<MROWS, 256>>>(pPre, hidden, gamma, beta, out);
}